// round 5
// baseline (speedup 1.0000x reference)
#include <cuda_runtime.h>
#include <math.h>
#include <stdint.h>

#define Bc 2
#define Nc 1024
#define Dc 512
#define Hc 8
#define DHc 64
#define HDc 512
#define FFc 2048
#define Mc (Bc*Nc)     /* 2048 rows */
#define BHc (Bc*Hc)    /* 16 batch-heads */
#define SCALEc 0.125f
#define BK 16
#define PAD 4

// ---------------- device scratch (static; no cudaMalloc allowed) --------------------
static __device__ __align__(256) float g_xn[Mc*Dc];
static __device__ __align__(256) float g_qkv[Mc*3*HDc];
static __device__ __align__(256) float g_q[BHc*Nc*DHc];
static __device__ __align__(256) float g_k[BHc*Nc*DHc];
static __device__ __align__(256) float g_v[BHc*Nc*DHc];
static __device__ __align__(256) float g_rcat[Mc*3*Dc];          // [r_t|r_c|r_p] 2048x1536
static __device__ __align__(256) float g_wall[3*Dc*4*HDc];       // 1536 x 2048
static __device__ __align__(256) float g_wsall[Mc*4*HDc];        // 2048 x 2048
static __device__ __align__(256) float g_wsr[4*BHc*Nc*DHc];      // per-layer (b,h,n,d)/3
static __device__ __align__(256) float g_ac[(size_t)BHc*Nc*Nc];
static __device__ __align__(256) float g_bdraw[(size_t)BHc*Nc*Nc];
static __device__ __align__(256) float g_attn[(size_t)BHc*Nc*Nc];
static __device__ __align__(256) float g_av[Mc*HDc];
static __device__ __align__(256) float g_h1[Mc*FFc];
static __device__ __align__(256) float g_x[Mc*Dc];
static __device__ __align__(256) float g_xmid[Mc*Dc];

// ---------------- tf32 helpers ------------------------------------------------------
__device__ __forceinline__ unsigned f2tf(float x) {
    unsigned u; asm("cvt.rna.tf32.f32 %0, %1;" : "=r"(u) : "f"(x)); return u;
}
__device__ __forceinline__ void mma8(float* c, const unsigned* a, const unsigned* b) {
    asm volatile("mma.sync.aligned.m16n8k8.row.col.f32.tf32.tf32.f32 "
        "{%0,%1,%2,%3}, {%4,%5,%6,%7}, {%8,%9}, {%0,%1,%2,%3};"
        : "+f"(c[0]), "+f"(c[1]), "+f"(c[2]), "+f"(c[3])
        : "r"(a[0]), "r"(a[1]), "r"(a[2]), "r"(a[3]), "r"(b[0]), "r"(b[1]));
}

// ---------------- unified tf32 tensor-core GEMM -------------------------------------
// C(MxN) = A(MxK) @ op(B);  TB=false: B is KxN row-major; TB=true: B is NxK row-major.
// grid: (N/BN, M/BM, batch); per-z pointer strides sA/sB/sC.
// mode: 0 plain, 1 +bias, 2 +bias+resid, 3 +bias then exact gelu,
//       4 attn_v epilogue: C[(bb*Nc + r)*HDc + h*DHc + c], bh = blockIdx.z
template<int BM, int BN, int WM, int WN, bool TB>
__global__ __launch_bounds__(256, 2) void tf32_gemm(
    const float* __restrict__ A, const float* __restrict__ B, float* __restrict__ C,
    int K, int lda, int ldb, int ldc,
    long long sA, long long sB, long long sC,
    const float* __restrict__ bias, const float* __restrict__ resid, int mode)
{
    constexpr int NWN = BN / WN;
    constexpr int MT = WM / 16;
    constexpr int NT = WN / 8;
    constexpr int IA = (BM * 4) / 256;
    constexpr int IB = (BN * 4) / 256;
    __shared__ unsigned As[2][BK][BM + PAD];
    __shared__ unsigned Bs[2][BK][BN + PAD];

    const float* Ab = A + (size_t)sA * blockIdx.z;
    const float* Bb = B + (size_t)sB * blockIdx.z;
    float* Cb = C + (size_t)sC * blockIdx.z;

    int tid = threadIdx.x;
    int lane = tid & 31, wid = tid >> 5;
    int wm = (wid / NWN) * WM, wn = (wid % NWN) * WN;
    int gid = lane >> 2, tig = lane & 3;
    int bm0 = blockIdx.y * BM, bn0 = blockIdx.x * BN;

    float acc[MT][NT][4];
#pragma unroll
    for (int i = 0; i < MT; i++)
#pragma unroll
        for (int j = 0; j < NT; j++)
#pragma unroll
            for (int t = 0; t < 4; t++) acc[i][j][t] = 0.f;

    float4 ra[IA], rb[IB];

    auto FETCH = [&](int k0) {
#pragma unroll
        for (int it = 0; it < IA; it++) {
            int idx = tid + it * 256;
            int m = idx >> 2, kc = (idx & 3) * 4;
            ra[it] = *(const float4*)(Ab + (size_t)(bm0 + m) * lda + k0 + kc);
        }
        if (!TB) {
#pragma unroll
            for (int it = 0; it < IB; it++) {
                int idx = tid + it * 256;
                int kr = idx / (BN / 4), n4 = (idx % (BN / 4)) * 4;
                rb[it] = *(const float4*)(Bb + (size_t)(k0 + kr) * ldb + bn0 + n4);
            }
        } else {
#pragma unroll
            for (int it = 0; it < IB; it++) {
                int idx = tid + it * 256;
                int n = idx >> 2, kc = (idx & 3) * 4;
                rb[it] = *(const float4*)(Bb + (size_t)(bn0 + n) * ldb + k0 + kc);
            }
        }
    };
    auto STORE = [&](int buf) {
#pragma unroll
        for (int it = 0; it < IA; it++) {
            int idx = tid + it * 256;
            int m = idx >> 2, kc = (idx & 3) * 4;
            As[buf][kc + 0][m] = f2tf(ra[it].x);
            As[buf][kc + 1][m] = f2tf(ra[it].y);
            As[buf][kc + 2][m] = f2tf(ra[it].z);
            As[buf][kc + 3][m] = f2tf(ra[it].w);
        }
        if (!TB) {
#pragma unroll
            for (int it = 0; it < IB; it++) {
                int idx = tid + it * 256;
                int kr = idx / (BN / 4), n4 = (idx % (BN / 4)) * 4;
                uint4 t;
                t.x = f2tf(rb[it].x); t.y = f2tf(rb[it].y);
                t.z = f2tf(rb[it].z); t.w = f2tf(rb[it].w);
                *(uint4*)&Bs[buf][kr][n4] = t;
            }
        } else {
#pragma unroll
            for (int it = 0; it < IB; it++) {
                int idx = tid + it * 256;
                int n = idx >> 2, kc = (idx & 3) * 4;
                Bs[buf][kc + 0][n] = f2tf(rb[it].x);
                Bs[buf][kc + 1][n] = f2tf(rb[it].y);
                Bs[buf][kc + 2][n] = f2tf(rb[it].z);
                Bs[buf][kc + 3][n] = f2tf(rb[it].w);
            }
        }
    };
    auto MMAKS = [&](int buf, int ks) {
        unsigned af[MT][4], bf[NT][2];
#pragma unroll
        for (int mt = 0; mt < MT; mt++) {
            int m = wm + mt * 16 + gid;
            af[mt][0] = As[buf][ks * 8 + tig][m];
            af[mt][1] = As[buf][ks * 8 + tig][m + 8];
            af[mt][2] = As[buf][ks * 8 + tig + 4][m];
            af[mt][3] = As[buf][ks * 8 + tig + 4][m + 8];
        }
#pragma unroll
        for (int nt = 0; nt < NT; nt++) {
            int n = wn + nt * 8 + gid;
            bf[nt][0] = Bs[buf][ks * 8 + tig][n];
            bf[nt][1] = Bs[buf][ks * 8 + tig + 4][n];
        }
#pragma unroll
        for (int mt = 0; mt < MT; mt++)
#pragma unroll
            for (int nt = 0; nt < NT; nt++)
                mma8(acc[mt][nt], af[mt], bf[nt]);
    };

    FETCH(0); STORE(0);
    __syncthreads();

    int nk = K / BK;
    for (int kt = 0; kt < nk; kt++) {
        int buf = kt & 1;
        bool has_next = (kt + 1 < nk);
        if (has_next) FETCH((kt + 1) * BK);   // LDGs in flight behind both ks halves
        MMAKS(buf, 0);
        if (has_next) STORE(buf ^ 1);         // STS drains behind second half
        MMAKS(buf, 1);
        __syncthreads();
    }

    // epilogue: acc[mt][nt] = {(r0,c0),(r0,c0+1),(r0+8,c0),(r0+8,c0+1)}
#pragma unroll
    for (int mt = 0; mt < MT; mt++) {
        int r0 = bm0 + wm + mt * 16 + gid;
#pragma unroll
        for (int nt = 0; nt < NT; nt++) {
            int c0 = bn0 + wn + nt * 8 + tig * 2;
#pragma unroll
            for (int half = 0; half < 2; half++) {
                int r = r0 + half * 8;
                float v0 = acc[mt][nt][half * 2 + 0];
                float v1 = acc[mt][nt][half * 2 + 1];
                if (mode == 4) {
                    int bb2 = blockIdx.z >> 3, h = blockIdx.z & 7;
                    size_t off = ((size_t)(bb2 * Nc + r)) * HDc + h * DHc + c0;
                    C[off] = v0; C[off + 1] = v1;
                } else {
                    size_t off = (size_t)r * ldc + c0;
                    if (mode == 1) { v0 += bias[c0]; v1 += bias[c0 + 1]; }
                    else if (mode == 2) { v0 += bias[c0] + resid[off]; v1 += bias[c0 + 1] + resid[off + 1]; }
                    else if (mode == 3) {
                        v0 += bias[c0]; v1 += bias[c0 + 1];
                        v0 = 0.5f * v0 * (1.f + erff(v0 * 0.70710678118654752f));
                        v1 = 0.5f * v1 * (1.f + erff(v1 * 0.70710678118654752f));
                    }
                    Cb[off] = v0; Cb[off + 1] = v1;
                }
            }
        }
    }
}

// ---------------- LayerNorm ---------------------------------------------------------
__global__ __launch_bounds__(128) void ln_kernel(
    const float* __restrict__ in, float* __restrict__ out,
    const float* __restrict__ g, const float* __restrict__ bta)
{
    int row = blockIdx.x;
    const float* xr = in + (size_t)row * Dc;
    float* orow = out + (size_t)row * Dc;
    int tid = threadIdx.x;
    float v[4]; float s = 0.f, ss = 0.f;
#pragma unroll
    for (int i = 0; i < 4; i++) { v[i] = xr[tid + i*128]; s += v[i]; ss += v[i]*v[i]; }
#pragma unroll
    for (int o = 16; o > 0; o >>= 1) {
        s  += __shfl_xor_sync(0xffffffffu, s, o);
        ss += __shfl_xor_sync(0xffffffffu, ss, o);
    }
    __shared__ float sh[8];
    int w = tid >> 5, lane = tid & 31;
    if (lane == 0) { sh[w] = s; sh[4+w] = ss; }
    __syncthreads();
    if (tid == 0) {
        float ts = sh[0]+sh[1]+sh[2]+sh[3];
        float tss = sh[4]+sh[5]+sh[6]+sh[7];
        sh[0] = ts; sh[1] = tss;
    }
    __syncthreads();
    float mean = sh[0] * (1.f/Dc);
    float var  = sh[1] * (1.f/Dc) - mean*mean;
    float inv  = rsqrtf(var + 1e-5f);
#pragma unroll
    for (int i = 0; i < 4; i++) {
        int c = tid + i*128;
        orow[c] = (v[i]-mean)*inv*g[c] + bta[c];
    }
}

// ---------------- split qkv -> (b,h,n,d), q gets +bias_pf (float4 over d) -----------
__global__ void split_qkv_kernel(
    const float* __restrict__ qkv, const float* __restrict__ bias_pf,
    float* __restrict__ q, float* __restrict__ k, float* __restrict__ v)
{
    int idx = blockIdx.x * blockDim.x + threadIdx.x;  // over B*H*N*(DH/4) = 256K
    int d4 = idx & 15;
    int n = (idx >> 4) & (Nc - 1);
    int h = (idx >> 14) & 7;
    int b = idx >> 17;
    size_t src = ((size_t)(b*Nc + n)) * (3*HDc) + h*DHc + d4*4;
    size_t dst = ((size_t)idx) * 4;
    float4 qv = *(const float4*)(qkv + src);
    float4 bp = *(const float4*)(bias_pf + h*DHc + d4*4);
    qv.x += bp.x; qv.y += bp.y; qv.z += bp.z; qv.w += bp.w;
    *(float4*)(q + dst) = qv;
    *(float4*)(k + dst) = *(const float4*)(qkv + src + HDc);
    *(float4*)(v + dst) = *(const float4*)(qkv + src + 2*HDc);
}

// ---------------- build [r_t|r_c|r_p] (2048 x 1536) ---------------------------------
__global__ void rcat_kernel(const float* __restrict__ rt, const float* __restrict__ rc,
                            const float* __restrict__ rp, float* __restrict__ out)
{
    int idx = blockIdx.x * blockDim.x + threadIdx.x;  // 2048*1536/4
    int row = idx / 384, c4 = idx % 384;
    const float* srcs[3] = {rt, rc, rp};
    const float* s = srcs[c4 >> 7];
    int c = (c4 & 127) * 4;
    *(float4*)(out + (size_t)idx*4) = *(const float4*)(s + (size_t)row*512 + c);
}

// ---------------- build stacked W (1536 x 2048): col block l = [wkt;wkc;wkp][l] -----
__global__ void wall_kernel(const float* __restrict__ wkt, const float* __restrict__ wkc,
                            const float* __restrict__ wkp, float* __restrict__ out)
{
    int idx = blockIdx.x * blockDim.x + threadIdx.x;  // 1536*2048/4
    int k = idx >> 9;
    int col4 = idx & 511;
    int l = col4 >> 7, c = (col4 & 127) * 4;
    const float* srcs[3] = {wkt, wkc, wkp};
    const float* s = srcs[k >> 9];
    int kk = k & 511;
    *(float4*)(out + (size_t)idx*4) =
        *(const float4*)(s + ((size_t)l*512 + kk) * 512 + c);
}

// ---------------- wsr for all layers: (l,b,h,n,d) = wsall[(b,n),(l,h,d)]/3 ----------
__global__ void wsr_all_kernel(const float* __restrict__ wsall, float* __restrict__ wsr)
{
    int idx = blockIdx.x * blockDim.x + threadIdx.x;  // 4*2^20/4 = 1M
    int d4 = idx & 15;
    int n = (idx >> 4) & (Nc - 1);
    int h = (idx >> 14) & 7;
    int b = (idx >> 17) & 1;
    int l = idx >> 18;
    float4 t = *(const float4*)(wsall + ((size_t)(b*Nc + n)) * 2048 + l*512 + h*64 + d4*4);
    t.x *= (1.0f/3.0f); t.y *= (1.0f/3.0f); t.z *= (1.0f/3.0f); t.w *= (1.0f/3.0f);
    *(float4*)(wsr + (size_t)idx*4) = t;
}

// ---------------- fused: dots=(AC+rel_shift(BD))*SCALE, softmax over heads ----------
// 4 consecutive j per thread: float4 AC loads / attn stores, scalar BD gathers.
__global__ void softmax_fused_kernel(const float* __restrict__ AC,
                                     const float* __restrict__ BD,
                                     float* __restrict__ attn)
{
    int t = blockIdx.x * blockDim.x + threadIdx.x;   // over B*N*(N/4) = 512K
    int j4 = (t & 255) * 4;
    int i = (t >> 8) & (Nc - 1);
    int b = t >> 18;
    size_t base = ((size_t)b * Hc) * Nc * Nc + (size_t)i * Nc + j4;
    const size_t stride = (size_t)Nc * Nc;
    float d[Hc][4];
#pragma unroll
    for (int h = 0; h < Hc; h++) {
        float4 acv = *(const float4*)(AC + base + h*stride);
        d[h][0] = acv.x; d[h][1] = acv.y; d[h][2] = acv.z; d[h][3] = acv.w;
    }
#pragma unroll
    for (int e = 0; e < 4; e++) {
        int j = j4 + e;
        int f = i * Nc + j + Nc;
        int i2 = f / (Nc + 1);
        int jj = f - i2 * (Nc + 1);
        size_t bd_off = ((size_t)b * Hc) * stride + (size_t)i2 * Nc + (jj - 1);
        if (jj != 0) {
#pragma unroll
            for (int h = 0; h < Hc; h++)
                d[h][e] = (d[h][e] + BD[bd_off + h*stride]) * SCALEc;
        } else {
#pragma unroll
            for (int h = 0; h < Hc; h++) d[h][e] *= SCALEc;
        }
    }
#pragma unroll
    for (int e = 0; e < 4; e++) {
        float m = d[0][e];
#pragma unroll
        for (int h = 1; h < Hc; h++) m = fmaxf(m, d[h][e]);
        float s = 0.f;
#pragma unroll
        for (int h = 0; h < Hc; h++) { d[h][e] = expf(d[h][e] - m); s += d[h][e]; }
        float inv = 1.f / s;
#pragma unroll
        for (int h = 0; h < Hc; h++) d[h][e] *= inv;
    }
#pragma unroll
    for (int h = 0; h < Hc; h++) {
        float4 o; o.x = d[h][0]; o.y = d[h][1]; o.z = d[h][2]; o.w = d[h][3];
        *(float4*)(attn + base + h*stride) = o;
    }
}

// ===================================================================================
extern "C" void kernel_launch(void* const* d_in, const int* in_sizes, int n_in,
                              void* d_out, int out_size)
{
    const float* x_in    = (const float*)d_in[0];
    const float* r_t     = (const float*)d_in[1];
    const float* r_c     = (const float*)d_in[2];
    const float* r_p     = (const float*)d_in[3];
    const float* bias_pf = (const float*)d_in[4];
    const float* ln1_g   = (const float*)d_in[5];
    const float* ln1_b   = (const float*)d_in[6];
    const float* w_qkv   = (const float*)d_in[7];
    const float* w_out   = (const float*)d_in[8];
    const float* b_out   = (const float*)d_in[9];
    const float* w_kt    = (const float*)d_in[10];
    const float* w_kc    = (const float*)d_in[11];
    const float* w_kp    = (const float*)d_in[12];
    const float* ln2_g   = (const float*)d_in[13];
    const float* ln2_b   = (const float*)d_in[14];
    const float* w_ff1   = (const float*)d_in[15];
    const float* b_ff1   = (const float*)d_in[16];
    const float* w_ff2   = (const float*)d_in[17];
    const float* b_ff2   = (const float*)d_in[18];
    float* out = (float*)d_out;

    float *xn, *qkv, *q, *k, *v, *rcat, *wall, *wsall, *wsr, *ac, *bdraw, *attnb,
          *av, *h1, *x, *xmid;
    cudaGetSymbolAddress((void**)&xn, g_xn);
    cudaGetSymbolAddress((void**)&qkv, g_qkv);
    cudaGetSymbolAddress((void**)&q, g_q);
    cudaGetSymbolAddress((void**)&k, g_k);
    cudaGetSymbolAddress((void**)&v, g_v);
    cudaGetSymbolAddress((void**)&rcat, g_rcat);
    cudaGetSymbolAddress((void**)&wall, g_wall);
    cudaGetSymbolAddress((void**)&wsall, g_wsall);
    cudaGetSymbolAddress((void**)&wsr, g_wsr);
    cudaGetSymbolAddress((void**)&ac, g_ac);
    cudaGetSymbolAddress((void**)&bdraw, g_bdraw);
    cudaGetSymbolAddress((void**)&attnb, g_attn);
    cudaGetSymbolAddress((void**)&av, g_av);
    cudaGetSymbolAddress((void**)&h1, g_h1);
    cudaGetSymbolAddress((void**)&x, g_x);
    cudaGetSymbolAddress((void**)&xmid, g_xmid);

    float* x_out    = out;
    float* attn_out = out + (size_t)Mc * Dc;

    // ---- upfront: all-layer relative-projection GEMM (layer-independent) ----------
    rcat_kernel<<<(Mc*3*Dc/4)/256, 256>>>(r_t, r_c, r_p, rcat);
    wall_kernel<<<(3*Dc*2048/4)/256, 256>>>(w_kt, w_kc, w_kp, wall);
    tf32_gemm<128,128,64,32,false><<<dim3(16,16), 256>>>(
        rcat, wall, wsall, 3*Dc, 3*Dc, 2048, 2048, 0,0,0, nullptr, nullptr, 0);
    wsr_all_kernel<<<(4*BHc*Nc*DHc/4)/256, 256>>>(wsall, wsr);

    const float* cur = x_in;
    for (int l = 0; l < 4; l++) {
        // LN1
        ln_kernel<<<Mc, 128>>>(cur, xn, ln1_g + l*Dc, ln1_b + l*Dc);
        // qkv = xn @ w_qkv[l]  (2048 x 1536, K=512)
        tf32_gemm<128,128,64,32,false><<<dim3(12,16), 256>>>(
            xn, w_qkv + (size_t)l*Dc*3*HDc, qkv, Dc, Dc, 3*HDc, 3*HDc,
            0,0,0, nullptr, nullptr, 0);
        split_qkv_kernel<<<(BHc*Nc*DHc/4)/256, 256>>>(qkv, bias_pf, q, k, v);
        // AC = Q K^T ; BDraw = Q Wsr^T (batched NT over 16 bh each)
        tf32_gemm<128,128,64,32,true><<<dim3(8,8,BHc), 256>>>(
            q, k, ac, DHc, DHc, DHc, Nc,
            (long long)Nc*DHc, (long long)Nc*DHc, (long long)Nc*Nc,
            nullptr, nullptr, 0);
        tf32_gemm<128,128,64,32,true><<<dim3(8,8,BHc), 256>>>(
            q, wsr + (size_t)l*BHc*Nc*DHc, bdraw, DHc, DHc, DHc, Nc,
            (long long)Nc*DHc, (long long)Nc*DHc, (long long)Nc*Nc,
            nullptr, nullptr, 0);
        // fused combine + rel_shift + softmax-over-heads
        float* attn = (l == 3) ? attn_out : attnb;
        softmax_fused_kernel<<<(int)(((size_t)Bc*Nc*Nc/4)/256), 256>>>(ac, bdraw, attn);
        // O = attn @ V  (batched NN, custom epilogue into (b,n,h*d))
        tf32_gemm<128,64,32,32,false><<<dim3(1,8,BHc), 256>>>(
            attn, v, av, Nc, Nc, DHc, HDc,
            (long long)Nc*Nc, (long long)Nc*DHc, 0,
            nullptr, nullptr, 4);
        // x = O @ w_out + b_out + x
        tf32_gemm<64,128,32,32,false><<<dim3(4,32), 256>>>(
            av, w_out + (size_t)l*HDc*Dc, xmid, HDc, HDc, Dc, Dc,
            0,0,0, b_out + l*Dc, cur, 2);
        // LN2
        ln_kernel<<<Mc, 128>>>(xmid, xn, ln2_g + l*Dc, ln2_b + l*Dc);
        // h1 = gelu(xn @ w_ff1 + b_ff1)
        tf32_gemm<128,128,64,32,false><<<dim3(16,16), 256>>>(
            xn, w_ff1 + (size_t)l*Dc*FFc, h1, Dc, Dc, FFc, FFc,
            0,0,0, b_ff1 + l*FFc, nullptr, 3);
        // x = h1 @ w_ff2 + b_ff2 + xmid
        float* xdst = (l == 3) ? x_out : x;
        tf32_gemm<64,128,32,32,false><<<dim3(4,32), 256>>>(
            h1, w_ff2 + (size_t)l*FFc*Dc, xdst, FFc, FFc, Dc, Dc,
            0,0,0, b_ff2 + l*Dc, xmid, 2);
        cur = x;
    }
}

// round 6
// speedup vs baseline: 1.5818x; 1.5818x over previous
#include <cuda_runtime.h>
#include <math.h>
#include <stdint.h>

#define Bc 2
#define Nc 1024
#define Dc 512
#define Hc 8
#define DHc 64
#define HDc 512
#define FFc 2048
#define Mc (Bc*Nc)     /* 2048 rows */
#define BHc (Bc*Hc)    /* 16 batch-heads */
#define SCALEc 0.125f
#define BK 16

// ---------------- device scratch (static; no cudaMalloc allowed) --------------------
static __device__ __align__(256) float g_xn[Mc*Dc];
static __device__ __align__(256) float g_qkv[Mc*3*HDc];
static __device__ __align__(256) float g_q[BHc*Nc*DHc];
static __device__ __align__(256) float g_k[BHc*Nc*DHc];
static __device__ __align__(256) float g_v[BHc*Nc*DHc];
static __device__ __align__(256) float g_rcat[Mc*3*Dc];
static __device__ __align__(256) float g_wall[3*Dc*4*HDc];
static __device__ __align__(256) float g_wsall[Mc*4*HDc];
static __device__ __align__(256) float g_wsr[4*BHc*Nc*DHc];
static __device__ __align__(256) float g_ac[(size_t)BHc*Nc*Nc];
static __device__ __align__(256) float g_bdraw[(size_t)BHc*Nc*Nc];
static __device__ __align__(256) float g_attn[(size_t)BHc*Nc*Nc];
static __device__ __align__(256) float g_av[Mc*HDc];
static __device__ __align__(256) float g_h1[Mc*FFc];
static __device__ __align__(256) float g_x[Mc*Dc];
static __device__ __align__(256) float g_xmid[Mc*Dc];
// rounded weight copies
static __device__ __align__(256) float g_wqkvr[4*Dc*3*HDc];
static __device__ __align__(256) float g_woutr[4*HDc*Dc];
static __device__ __align__(256) float g_wff1r[4*Dc*FFc];
static __device__ __align__(256) float g_wff2r[4*FFc*Dc];

// ---------------- helpers -----------------------------------------------------------
__device__ __forceinline__ float tfr(float x) {
    unsigned u; asm("cvt.rna.tf32.f32 %0, %1;" : "=r"(u) : "f"(x));
    return __uint_as_float(u);
}
__device__ __forceinline__ void mma8(float* c, const unsigned* a, const unsigned* b) {
    asm volatile("mma.sync.aligned.m16n8k8.row.col.f32.tf32.tf32.f32 "
        "{%0,%1,%2,%3}, {%4,%5,%6,%7}, {%8,%9}, {%0,%1,%2,%3};"
        : "+f"(c[0]), "+f"(c[1]), "+f"(c[2]), "+f"(c[3])
        : "r"(a[0]), "r"(a[1]), "r"(a[2]), "r"(a[3]), "r"(b[0]), "r"(b[1]));
}
__device__ __forceinline__ void cp16(void* dst, const void* src) {
    unsigned a = (unsigned)__cvta_generic_to_shared(dst);
    asm volatile("cp.async.cg.shared.global [%0], [%1], 16;\n" :: "r"(a), "l"(src));
}
#define CP_COMMIT() asm volatile("cp.async.commit_group;\n" ::: "memory")
#define CP_WAIT1()  asm volatile("cp.async.wait_group 1;\n" ::: "memory")

// ---------------- tf32 tensor-core GEMM, cp.async 3-stage pipeline ------------------
// Inputs A and B must already be tf32-rounded f32. C = A(MxK) @ op(B).
// TB=false: B is KxN row-major; TB=true: B is NxK row-major.
// mode: 0 plain, 1 +bias, 2 +bias+resid, 3 +bias,gelu,round(tf32),
//       4 attn_v epilogue (rounded): C[(bb*Nc+r)*HDc + h*DHc + c], bh = blockIdx.z
template<int BM, int BN, int WM, int WN, bool TB>
__global__ __launch_bounds__(256, 2) void tf32_gemm(
    const float* __restrict__ A, const float* __restrict__ B, float* __restrict__ C,
    int K, int lda, int ldb, int ldc,
    long long sA, long long sB, long long sC,
    const float* __restrict__ bias, const float* __restrict__ resid, int mode)
{
    constexpr int NWN = BN / WN;
    constexpr int MT = WM / 16;
    constexpr int NT = WN / 8;
    constexpr int IAc = (BM * 4) / 256;           // 16B chunks per thread for A
    constexpr int IBc = (BN * 4) / 256;           // same count for B either way
    __shared__ unsigned As[3][BM * BK];           // [r][k^((r&6)<<1)]
    __shared__ unsigned Bs[3][BN * BK];           // !TB: [k][n^((k&3)<<3)] ; TB: [n][k^((n&6)<<1)]

    const float* Ab = A + (size_t)sA * blockIdx.z;
    const float* Bb = B + (size_t)sB * blockIdx.z;
    float* Cb = C + (size_t)sC * blockIdx.z;

    int tid = threadIdx.x;
    int lane = tid & 31, wid = tid >> 5;
    int wm = (wid / NWN) * WM, wn = (wid % NWN) * WN;
    int gid = lane >> 2, tig = lane & 3;
    int bm0 = blockIdx.y * BM, bn0 = blockIdx.x * BN;

    float acc[MT][NT][4];
#pragma unroll
    for (int i = 0; i < MT; i++)
#pragma unroll
        for (int j = 0; j < NT; j++)
#pragma unroll
            for (int t = 0; t < 4; t++) acc[i][j][t] = 0.f;

    auto COPY = [&](int s, int k0) {
#pragma unroll
        for (int it = 0; it < IAc; it++) {
            int ch = tid + it * 256;
            int r = ch >> 2, c4 = (ch & 3) << 2;
            int col = c4 ^ ((r & 6) << 1);
            cp16(&As[s][r * BK + col], Ab + (size_t)(bm0 + r) * lda + k0 + c4);
        }
        if (!TB) {
#pragma unroll
            for (int it = 0; it < IBc; it++) {
                int ch = tid + it * 256;
                int r = ch / (BN / 4), c4 = (ch % (BN / 4)) << 2;
                int col = c4 ^ ((r & 3) << 3);
                cp16(&Bs[s][r * BN + col], Bb + (size_t)(k0 + r) * ldb + bn0 + c4);
            }
        } else {
#pragma unroll
            for (int it = 0; it < IBc; it++) {
                int ch = tid + it * 256;
                int r = ch >> 2, c4 = (ch & 3) << 2;
                int col = c4 ^ ((r & 6) << 1);
                cp16(&Bs[s][r * BK + col], Bb + (size_t)(bn0 + r) * ldb + k0 + c4);
            }
        }
    };
    auto MMAKS = [&](int buf, int ks) {
        unsigned af[MT][4], bf[NT][2];
        int k0 = ks * 8;
#pragma unroll
        for (int mt = 0; mt < MT; mt++) {
            int m = wm + mt * 16 + gid;
            int sw = (m & 6) << 1;                 // same for m and m+8
            af[mt][0] = As[buf][m * BK + ((k0 + tig) ^ sw)];
            af[mt][1] = As[buf][(m + 8) * BK + ((k0 + tig) ^ sw)];
            af[mt][2] = As[buf][m * BK + ((k0 + tig + 4) ^ sw)];
            af[mt][3] = As[buf][(m + 8) * BK + ((k0 + tig + 4) ^ sw)];
        }
#pragma unroll
        for (int nt = 0; nt < NT; nt++) {
            int n = wn + nt * 8 + gid;
            if (!TB) {
                int col = n ^ (tig << 3);          // (k&3)==tig for both k rows
                bf[nt][0] = Bs[buf][(k0 + tig) * BN + col];
                bf[nt][1] = Bs[buf][(k0 + tig + 4) * BN + col];
            } else {
                int sw = (n & 6) << 1;
                bf[nt][0] = Bs[buf][n * BK + ((k0 + tig) ^ sw)];
                bf[nt][1] = Bs[buf][n * BK + ((k0 + tig + 4) ^ sw)];
            }
        }
#pragma unroll
        for (int mt = 0; mt < MT; mt++)
#pragma unroll
            for (int nt = 0; nt < NT; nt++)
                mma8(acc[mt][nt], af[mt], bf[nt]);
    };

    int nk = K / BK;                               // K >= 64 always here
    COPY(0, 0);       CP_COMMIT();
    COPY(1, BK);      CP_COMMIT();
    for (int kt = 0; kt < nk; kt++) {
        CP_WAIT1();
        __syncthreads();
        int nxt = kt + 2;
        if (nxt < nk) COPY(nxt - (nxt / 3) * 3, nxt * BK);
        CP_COMMIT();
        int buf = kt - (kt / 3) * 3;
        MMAKS(buf, 0);
        MMAKS(buf, 1);
    }

    // epilogue: acc[mt][nt] = {(r0,c0),(r0,c0+1),(r0+8,c0),(r0+8,c0+1)}
#pragma unroll
    for (int mt = 0; mt < MT; mt++) {
        int r0 = bm0 + wm + mt * 16 + gid;
#pragma unroll
        for (int nt = 0; nt < NT; nt++) {
            int c0 = bn0 + wn + nt * 8 + tig * 2;
#pragma unroll
            for (int half = 0; half < 2; half++) {
                int r = r0 + half * 8;
                float v0 = acc[mt][nt][half * 2 + 0];
                float v1 = acc[mt][nt][half * 2 + 1];
                if (mode == 4) {
                    int bb2 = blockIdx.z >> 3, h = blockIdx.z & 7;
                    size_t off = ((size_t)(bb2 * Nc + r)) * HDc + h * DHc + c0;
                    C[off] = tfr(v0); C[off + 1] = tfr(v1);
                } else {
                    size_t off = (size_t)r * ldc + c0;
                    if (mode == 1) { v0 += bias[c0]; v1 += bias[c0 + 1]; }
                    else if (mode == 2) { v0 += bias[c0] + resid[off]; v1 += bias[c0 + 1] + resid[off + 1]; }
                    else if (mode == 3) {
                        v0 += bias[c0]; v1 += bias[c0 + 1];
                        v0 = tfr(0.5f * v0 * (1.f + erff(v0 * 0.70710678118654752f)));
                        v1 = tfr(0.5f * v1 * (1.f + erff(v1 * 0.70710678118654752f)));
                    }
                    Cb[off] = v0; Cb[off + 1] = v1;
                }
            }
        }
    }
}

// ---------------- LayerNorm (output tf32-rounded; feeds GEMMs only) -----------------
__global__ __launch_bounds__(128) void ln_kernel(
    const float* __restrict__ in, float* __restrict__ out,
    const float* __restrict__ g, const float* __restrict__ bta)
{
    int row = blockIdx.x;
    const float* xr = in + (size_t)row * Dc;
    float* orow = out + (size_t)row * Dc;
    int tid = threadIdx.x;
    float v[4]; float s = 0.f, ss = 0.f;
#pragma unroll
    for (int i = 0; i < 4; i++) { v[i] = xr[tid + i*128]; s += v[i]; ss += v[i]*v[i]; }
#pragma unroll
    for (int o = 16; o > 0; o >>= 1) {
        s  += __shfl_xor_sync(0xffffffffu, s, o);
        ss += __shfl_xor_sync(0xffffffffu, ss, o);
    }
    __shared__ float sh[8];
    int w = tid >> 5, lane = tid & 31;
    if (lane == 0) { sh[w] = s; sh[4+w] = ss; }
    __syncthreads();
    if (tid == 0) {
        float ts = sh[0]+sh[1]+sh[2]+sh[3];
        float tss = sh[4]+sh[5]+sh[6]+sh[7];
        sh[0] = ts; sh[1] = tss;
    }
    __syncthreads();
    float mean = sh[0] * (1.f/Dc);
    float var  = sh[1] * (1.f/Dc) - mean*mean;
    float inv  = rsqrtf(var + 1e-5f);
#pragma unroll
    for (int i = 0; i < 4; i++) {
        int c = tid + i*128;
        orow[c] = tfr((v[i]-mean)*inv*g[c] + bta[c]);
    }
}

// ---------------- tf32 round-copy (weights), float4 ---------------------------------
__global__ void round_kernel(const float* __restrict__ in, float* __restrict__ out)
{
    int i = blockIdx.x * blockDim.x + threadIdx.x;
    float4 t = ((const float4*)in)[i];
    t.x = tfr(t.x); t.y = tfr(t.y); t.z = tfr(t.z); t.w = tfr(t.w);
    ((float4*)out)[i] = t;
}

// ---------------- split qkv -> (b,h,n,d), q += bias_pf, all rounded -----------------
__global__ void split_qkv_kernel(
    const float* __restrict__ qkv, const float* __restrict__ bias_pf,
    float* __restrict__ q, float* __restrict__ k, float* __restrict__ v)
{
    int idx = blockIdx.x * blockDim.x + threadIdx.x;  // B*H*N*(DH/4)
    int d4 = idx & 15;
    int n = (idx >> 4) & (Nc - 1);
    int h = (idx >> 14) & 7;
    int b = idx >> 17;
    size_t src = ((size_t)(b*Nc + n)) * (3*HDc) + h*DHc + d4*4;
    size_t dst = ((size_t)idx) * 4;
    float4 qv = *(const float4*)(qkv + src);
    float4 bp = *(const float4*)(bias_pf + h*DHc + d4*4);
    qv.x = tfr(qv.x + bp.x); qv.y = tfr(qv.y + bp.y);
    qv.z = tfr(qv.z + bp.z); qv.w = tfr(qv.w + bp.w);
    *(float4*)(q + dst) = qv;
    float4 kv = *(const float4*)(qkv + src + HDc);
    kv.x = tfr(kv.x); kv.y = tfr(kv.y); kv.z = tfr(kv.z); kv.w = tfr(kv.w);
    *(float4*)(k + dst) = kv;
    float4 vv = *(const float4*)(qkv + src + 2*HDc);
    vv.x = tfr(vv.x); vv.y = tfr(vv.y); vv.z = tfr(vv.z); vv.w = tfr(vv.w);
    *(float4*)(v + dst) = vv;
}

// ---------------- build [r_t|r_c|r_p] rounded (2048 x 1536) -------------------------
__global__ void rcat_kernel(const float* __restrict__ rt, const float* __restrict__ rc,
                            const float* __restrict__ rp, float* __restrict__ out)
{
    int idx = blockIdx.x * blockDim.x + threadIdx.x;
    int row = idx / 384, c4 = idx % 384;
    const float* srcs[3] = {rt, rc, rp};
    const float* s = srcs[c4 >> 7];
    int c = (c4 & 127) * 4;
    float4 t = *(const float4*)(s + (size_t)row*512 + c);
    t.x = tfr(t.x); t.y = tfr(t.y); t.z = tfr(t.z); t.w = tfr(t.w);
    *(float4*)(out + (size_t)idx*4) = t;
}

// ---------------- build stacked W rounded (1536 x 2048) -----------------------------
__global__ void wall_kernel(const float* __restrict__ wkt, const float* __restrict__ wkc,
                            const float* __restrict__ wkp, float* __restrict__ out)
{
    int idx = blockIdx.x * blockDim.x + threadIdx.x;
    int k = idx >> 9;
    int col4 = idx & 511;
    int l = col4 >> 7, c = (col4 & 127) * 4;
    const float* srcs[3] = {wkt, wkc, wkp};
    const float* s = srcs[k >> 9];
    int kk = k & 511;
    float4 t = *(const float4*)(s + ((size_t)l*512 + kk) * 512 + c);
    t.x = tfr(t.x); t.y = tfr(t.y); t.z = tfr(t.z); t.w = tfr(t.w);
    *(float4*)(out + (size_t)idx*4) = t;
}

// ---------------- wsr all layers, /3, rounded ---------------------------------------
__global__ void wsr_all_kernel(const float* __restrict__ wsall, float* __restrict__ wsr)
{
    int idx = blockIdx.x * blockDim.x + threadIdx.x;
    int d4 = idx & 15;
    int n = (idx >> 4) & (Nc - 1);
    int h = (idx >> 14) & 7;
    int b = (idx >> 17) & 1;
    int l = idx >> 18;
    float4 t = *(const float4*)(wsall + ((size_t)(b*Nc + n)) * 2048 + l*512 + h*64 + d4*4);
    t.x = tfr(t.x * (1.0f/3.0f)); t.y = tfr(t.y * (1.0f/3.0f));
    t.z = tfr(t.z * (1.0f/3.0f)); t.w = tfr(t.w * (1.0f/3.0f));
    *(float4*)(wsr + (size_t)idx*4) = t;
}

// ---------------- fused combine + rel_shift + softmax over heads --------------------
// attn gets tf32-rounded probs (GEMM input); attn_raw (if non-null) gets raw probs.
__global__ void softmax_fused_kernel(const float* __restrict__ AC,
                                     const float* __restrict__ BD,
                                     float* __restrict__ attn,
                                     float* __restrict__ attn_raw)
{
    int t = blockIdx.x * blockDim.x + threadIdx.x;   // B*N*(N/4)
    int j4 = (t & 255) * 4;
    int i = (t >> 8) & (Nc - 1);
    int b = t >> 18;
    size_t base = ((size_t)b * Hc) * Nc * Nc + (size_t)i * Nc + j4;
    const size_t stride = (size_t)Nc * Nc;
    float d[Hc][4];
#pragma unroll
    for (int h = 0; h < Hc; h++) {
        float4 acv = *(const float4*)(AC + base + h*stride);
        d[h][0] = acv.x; d[h][1] = acv.y; d[h][2] = acv.z; d[h][3] = acv.w;
    }
#pragma unroll
    for (int e = 0; e < 4; e++) {
        int j = j4 + e;
        int f = i * Nc + j + Nc;
        int i2 = f / (Nc + 1);
        int jj = f - i2 * (Nc + 1);
        size_t bd_off = ((size_t)b * Hc) * stride + (size_t)i2 * Nc + (jj - 1);
        if (jj != 0) {
#pragma unroll
            for (int h = 0; h < Hc; h++)
                d[h][e] = (d[h][e] + BD[bd_off + h*stride]) * SCALEc;
        } else {
#pragma unroll
            for (int h = 0; h < Hc; h++) d[h][e] *= SCALEc;
        }
    }
#pragma unroll
    for (int e = 0; e < 4; e++) {
        float m = d[0][e];
#pragma unroll
        for (int h = 1; h < Hc; h++) m = fmaxf(m, d[h][e]);
        float s = 0.f;
#pragma unroll
        for (int h = 0; h < Hc; h++) { d[h][e] = expf(d[h][e] - m); s += d[h][e]; }
        float inv = 1.f / s;
#pragma unroll
        for (int h = 0; h < Hc; h++) d[h][e] *= inv;
    }
#pragma unroll
    for (int h = 0; h < Hc; h++) {
        float4 o;
        if (attn_raw) {
            o.x = d[h][0]; o.y = d[h][1]; o.z = d[h][2]; o.w = d[h][3];
            *(float4*)(attn_raw + base + h*stride) = o;
        }
        o.x = tfr(d[h][0]); o.y = tfr(d[h][1]); o.z = tfr(d[h][2]); o.w = tfr(d[h][3]);
        *(float4*)(attn + base + h*stride) = o;
    }
}

// ===================================================================================
extern "C" void kernel_launch(void* const* d_in, const int* in_sizes, int n_in,
                              void* d_out, int out_size)
{
    const float* x_in    = (const float*)d_in[0];
    const float* r_t     = (const float*)d_in[1];
    const float* r_c     = (const float*)d_in[2];
    const float* r_p     = (const float*)d_in[3];
    const float* bias_pf = (const float*)d_in[4];
    const float* ln1_g   = (const float*)d_in[5];
    const float* ln1_b   = (const float*)d_in[6];
    const float* w_qkv   = (const float*)d_in[7];
    const float* w_out   = (const float*)d_in[8];
    const float* b_out   = (const float*)d_in[9];
    const float* w_kt    = (const float*)d_in[10];
    const float* w_kc    = (const float*)d_in[11];
    const float* w_kp    = (const float*)d_in[12];
    const float* ln2_g   = (const float*)d_in[13];
    const float* ln2_b   = (const float*)d_in[14];
    const float* w_ff1   = (const float*)d_in[15];
    const float* b_ff1   = (const float*)d_in[16];
    const float* w_ff2   = (const float*)d_in[17];
    const float* b_ff2   = (const float*)d_in[18];
    float* out = (float*)d_out;

    float *xn, *qkv, *q, *k, *v, *rcat, *wall, *wsall, *wsr, *ac, *bdraw, *attnb,
          *av, *h1, *x, *xmid, *wqkvr, *woutr, *wff1r, *wff2r;
    cudaGetSymbolAddress((void**)&xn, g_xn);
    cudaGetSymbolAddress((void**)&qkv, g_qkv);
    cudaGetSymbolAddress((void**)&q, g_q);
    cudaGetSymbolAddress((void**)&k, g_k);
    cudaGetSymbolAddress((void**)&v, g_v);
    cudaGetSymbolAddress((void**)&rcat, g_rcat);
    cudaGetSymbolAddress((void**)&wall, g_wall);
    cudaGetSymbolAddress((void**)&wsall, g_wsall);
    cudaGetSymbolAddress((void**)&wsr, g_wsr);
    cudaGetSymbolAddress((void**)&ac, g_ac);
    cudaGetSymbolAddress((void**)&bdraw, g_bdraw);
    cudaGetSymbolAddress((void**)&attnb, g_attn);
    cudaGetSymbolAddress((void**)&av, g_av);
    cudaGetSymbolAddress((void**)&h1, g_h1);
    cudaGetSymbolAddress((void**)&x, g_x);
    cudaGetSymbolAddress((void**)&xmid, g_xmid);
    cudaGetSymbolAddress((void**)&wqkvr, g_wqkvr);
    cudaGetSymbolAddress((void**)&woutr, g_woutr);
    cudaGetSymbolAddress((void**)&wff1r, g_wff1r);
    cudaGetSymbolAddress((void**)&wff2r, g_wff2r);

    float* x_out    = out;
    float* attn_out = out + (size_t)Mc * Dc;

    // ---- weight round-copies (tf32) ----
    round_kernel<<<(4*Dc*3*HDc/4)/256, 256>>>(w_qkv, wqkvr);
    round_kernel<<<(4*HDc*Dc/4)/256, 256>>>(w_out, woutr);
    round_kernel<<<(4*Dc*FFc/4)/256, 256>>>(w_ff1, wff1r);
    round_kernel<<<(4*FFc*Dc/4)/256, 256>>>(w_ff2, wff2r);

    // ---- upfront: all-layer relative-projection GEMM ----
    rcat_kernel<<<(Mc*3*Dc/4)/256, 256>>>(r_t, r_c, r_p, rcat);
    wall_kernel<<<(3*Dc*2048/4)/256, 256>>>(w_kt, w_kc, w_kp, wall);
    tf32_gemm<128,128,64,32,false><<<dim3(16,16), 256>>>(
        rcat, wall, wsall, 3*Dc, 3*Dc, 2048, 2048, 0,0,0, nullptr, nullptr, 0);
    wsr_all_kernel<<<(4*BHc*Nc*DHc/4)/256, 256>>>(wsall, wsr);

    const float* cur = x_in;
    for (int l = 0; l < 4; l++) {
        ln_kernel<<<Mc, 128>>>(cur, xn, ln1_g + l*Dc, ln1_b + l*Dc);
        tf32_gemm<128,128,64,32,false><<<dim3(12,16), 256>>>(
            xn, wqkvr + (size_t)l*Dc*3*HDc, qkv, Dc, Dc, 3*HDc, 3*HDc,
            0,0,0, nullptr, nullptr, 0);
        split_qkv_kernel<<<(BHc*Nc*DHc/4)/256, 256>>>(qkv, bias_pf, q, k, v);
        tf32_gemm<128,128,64,32,true><<<dim3(8,8,BHc), 256>>>(
            q, k, ac, DHc, DHc, DHc, Nc,
            (long long)Nc*DHc, (long long)Nc*DHc, (long long)Nc*Nc,
            nullptr, nullptr, 0);
        tf32_gemm<128,128,64,32,true><<<dim3(8,8,BHc), 256>>>(
            q, wsr + (size_t)l*BHc*Nc*DHc, bdraw, DHc, DHc, DHc, Nc,
            (long long)Nc*DHc, (long long)Nc*DHc, (long long)Nc*Nc,
            nullptr, nullptr, 0);
        softmax_fused_kernel<<<(int)(((size_t)Bc*Nc*Nc/4)/256), 256>>>(
            ac, bdraw, attnb, (l == 3) ? attn_out : nullptr);
        tf32_gemm<128,64,32,32,false><<<dim3(1,8,BHc), 256>>>(
            attnb, v, av, Nc, Nc, DHc, HDc,
            (long long)Nc*Nc, (long long)Nc*DHc, 0,
            nullptr, nullptr, 4);
        tf32_gemm<64,128,32,32,false><<<dim3(4,32), 256>>>(
            av, woutr + (size_t)l*HDc*Dc, xmid, HDc, HDc, Dc, Dc,
            0,0,0, b_out + l*Dc, cur, 2);
        ln_kernel<<<Mc, 128>>>(xmid, xn, ln2_g + l*Dc, ln2_b + l*Dc);
        tf32_gemm<128,128,64,32,false><<<dim3(16,16), 256>>>(
            xn, wff1r + (size_t)l*Dc*FFc, h1, Dc, Dc, FFc, FFc,
            0,0,0, b_ff1 + l*FFc, nullptr, 3);
        float* xdst = (l == 3) ? x_out : x;
        tf32_gemm<64,128,32,32,false><<<dim3(4,32), 256>>>(
            h1, wff2r + (size_t)l*FFc*Dc, xdst, FFc, FFc, Dc, Dc,
            0,0,0, b_ff2 + l*Dc, xmid, 2);
        cur = x;
    }
}

// round 7
// speedup vs baseline: 2.6376x; 1.6675x over previous
#include <cuda_runtime.h>
#include <cuda_fp16.h>
#include <math.h>
#include <stdint.h>

#define Bc 2
#define Nc 1024
#define Dc 512
#define Hc 8
#define DHc 64
#define HDc 512
#define FFc 2048
#define Mc (Bc*Nc)
#define BHc (Bc*Hc)
#define SCALEc 0.125f

// ---------------- device scratch ----------------------------------------------------
static __device__ __align__(256) __half g_xn[Mc*Dc];
static __device__ __align__(256) float  g_qkv[Mc*3*HDc];
static __device__ __align__(256) __half g_q[BHc*Nc*DHc];
static __device__ __align__(256) __half g_kw[BHc*2*Nc*DHc];   // rows 0..1023 = K, 1024.. = Wsr/3
static __device__ __align__(256) __half g_v[BHc*Nc*DHc];
static __device__ __align__(256) __half g_rcat[Mc*3*Dc];
static __device__ __align__(256) __half g_wall[3*Dc*4*HDc];
static __device__ __align__(256) float  g_wsall[Mc*4*HDc];
static __device__ __align__(256) float  g_sc[(size_t)BHc*Nc*2*Nc];   // [bh][i][2048]
static __device__ __align__(256) __half g_attn[(size_t)BHc*Nc*Nc];
static __device__ __align__(256) __half g_av[Mc*HDc];
static __device__ __align__(256) __half g_h1[Mc*FFc];
static __device__ __align__(256) float  g_x[Mc*Dc];
static __device__ __align__(256) float  g_xmid[Mc*Dc];
static __device__ __align__(256) __half g_wqkvh[4*Dc*3*HDc];
static __device__ __align__(256) __half g_wouth[4*HDc*Dc];
static __device__ __align__(256) __half g_wff1h[4*Dc*FFc];
static __device__ __align__(256) __half g_wff2h[4*FFc*Dc];

// ---------------- asm helpers -------------------------------------------------------
__device__ __forceinline__ void mma16(float* c, const unsigned* a, const unsigned* b) {
    asm volatile("mma.sync.aligned.m16n8k16.row.col.f32.f16.f16.f32 "
        "{%0,%1,%2,%3}, {%4,%5,%6,%7}, {%8,%9}, {%0,%1,%2,%3};"
        : "+f"(c[0]), "+f"(c[1]), "+f"(c[2]), "+f"(c[3])
        : "r"(a[0]), "r"(a[1]), "r"(a[2]), "r"(a[3]), "r"(b[0]), "r"(b[1]));
}
__device__ __forceinline__ void ldm_x4(unsigned* r, unsigned addr) {
    asm volatile("ldmatrix.sync.aligned.m8n8.x4.shared.b16 {%0,%1,%2,%3}, [%4];"
        : "=r"(r[0]), "=r"(r[1]), "=r"(r[2]), "=r"(r[3]) : "r"(addr));
}
__device__ __forceinline__ void ldm_x2(unsigned* r, unsigned addr) {
    asm volatile("ldmatrix.sync.aligned.m8n8.x2.shared.b16 {%0,%1}, [%2];"
        : "=r"(r[0]), "=r"(r[1]) : "r"(addr));
}
__device__ __forceinline__ void ldm_x2t(unsigned* r, unsigned addr) {
    asm volatile("ldmatrix.sync.aligned.m8n8.x2.trans.shared.b16 {%0,%1}, [%2];"
        : "=r"(r[0]), "=r"(r[1]) : "r"(addr));
}
__device__ __forceinline__ void cp16s(unsigned dst, const void* src) {
    asm volatile("cp.async.cg.shared.global [%0], [%1], 16;\n" :: "r"(dst), "l"(src));
}
#define CP_COMMIT() asm volatile("cp.async.commit_group;\n" ::: "memory")
#define CP_WAIT1()  asm volatile("cp.async.wait_group 1;\n" ::: "memory")

__device__ __forceinline__ void stC(float* p, float v0, float v1) {
    *(float2*)p = make_float2(v0, v1);
}
__device__ __forceinline__ void stC(__half* p, float v0, float v1) {
    *(__half2*)p = __floats2half2_rn(v0, v1);
}

// ---------------- fp16 tensor-core GEMM (m16n8k16 + ldmatrix + cp.async x3) ---------
// C(MxN) = A(MxK) @ op(B).  TB=false: B KxN row-major; TB=true: B NxK row-major.
// mode: 0 plain, 1 +bias, 2 +bias+resid(f32), 3 +bias,gelu, 4 attn_v scatter epilogue
template<int BM, int BN, int WM, int WN, bool TB, typename CT>
__global__ __launch_bounds__(256, 2) void h_gemm(
    const __half* __restrict__ A, const __half* __restrict__ B, CT* __restrict__ C,
    int K, int lda, int ldb, int ldc,
    long long sA, long long sB, long long sC,
    const float* __restrict__ bias, const float* __restrict__ resid, int mode)
{
    constexpr int NWN = BN / WN;
    constexpr int MT = WM / 16;
    constexpr int NT = WN / 8;
    constexpr int IAc = (BM * 4) / 256;
    constexpr int IBc = (BN * 4) / 256;
    __shared__ __half As[3][BM * 32];
    __shared__ __half Bs[3][BN * 32];

    const __half* Ab = A + (size_t)sA * blockIdx.z;
    const __half* Bb = B + (size_t)sB * blockIdx.z;
    CT* Cb = C + (size_t)sC * blockIdx.z;

    int tid = threadIdx.x;
    int lane = tid & 31, wid = tid >> 5;
    int wm = (wid / NWN) * WM, wn = (wid % NWN) * WN;
    int gid = lane >> 2, tig = lane & 3;
    int bm0 = blockIdx.y * BM, bn0 = blockIdx.x * BN;

    unsigned sAs = (unsigned)__cvta_generic_to_shared(&As[0][0]);
    unsigned sBs = (unsigned)__cvta_generic_to_shared(&Bs[0][0]);

    float acc[MT][NT][4];
#pragma unroll
    for (int i = 0; i < MT; i++)
#pragma unroll
        for (int j = 0; j < NT; j++)
#pragma unroll
            for (int t = 0; t < 4; t++) acc[i][j][t] = 0.f;

    auto COPY = [&](int st, int k0) {
#pragma unroll
        for (int it = 0; it < IAc; it++) {
            int ch = tid + it * 256;
            int m = ch >> 2, c = ch & 3;
            int cc = c ^ ((m >> 1) & 3);
            cp16s(sAs + (st * BM * 32 + m * 32 + cc * 8) * 2,
                  Ab + (size_t)(bm0 + m) * lda + k0 + c * 8);
        }
        if (TB) {
#pragma unroll
            for (int it = 0; it < IBc; it++) {
                int ch = tid + it * 256;
                int n = ch >> 2, c = ch & 3;
                int cc = c ^ ((n >> 1) & 3);
                cp16s(sBs + (st * BN * 32 + n * 32 + cc * 8) * 2,
                      Bb + (size_t)(bn0 + n) * ldb + k0 + c * 8);
            }
        } else {
#pragma unroll
            for (int it = 0; it < IBc; it++) {
                int ch = tid + it * 256;
                int k = ch / (BN / 8), nc = ch % (BN / 8);
                int cc = nc ^ (k & 7);
                cp16s(sBs + (st * BN * 32 + k * BN + cc * 8) * 2,
                      Bb + (size_t)(k0 + k) * ldb + bn0 + nc * 8);
            }
        }
    };
    auto MMASTEP = [&](int st, int s) {
        unsigned af[MT][4], bf[NT][2];
        unsigned abase = sAs + st * (BM * 32 * 2);
        unsigned bbase = sBs + st * (BN * 32 * 2);
        int la = lane & 7, t4 = lane >> 3;
#pragma unroll
        for (int mt = 0; mt < MT; mt++) {
            int m = wm + mt * 16 + (t4 & 1) * 8 + la;
            int c = 2 * s + (t4 >> 1);
            ldm_x4(af[mt], abase + (m * 32 + ((c ^ ((m >> 1) & 3)) << 3)) * 2);
        }
        if (TB) {
            int l2 = lane & 15;
#pragma unroll
            for (int nt = 0; nt < NT; nt++) {
                int n = wn + nt * 8 + (l2 & 7);
                int c = 2 * s + (l2 >> 3);
                ldm_x2(bf[nt], bbase + (n * 32 + ((c ^ ((n >> 1) & 3)) << 3)) * 2);
            }
        } else {
            int kk = 16 * s + (lane & 15);
#pragma unroll
            for (int nt = 0; nt < NT; nt++) {
                int nc = (wn + nt * 8) >> 3;
                ldm_x2t(bf[nt], bbase + (kk * BN + ((nc ^ (kk & 7)) << 3)) * 2);
            }
        }
#pragma unroll
        for (int mt = 0; mt < MT; mt++)
#pragma unroll
            for (int nt = 0; nt < NT; nt++)
                mma16(acc[mt][nt], af[mt], bf[nt]);
    };

    int nk = K >> 5;
    COPY(0, 0);  CP_COMMIT();
    COPY(1, 32); CP_COMMIT();
    for (int kt = 0; kt < nk; kt++) {
        CP_WAIT1();
        __syncthreads();
        int nxt = kt + 2;
        if (nxt < nk) COPY(nxt - (nxt / 3) * 3, nxt << 5);
        CP_COMMIT();
        int buf = kt - (kt / 3) * 3;
        MMASTEP(buf, 0);
        MMASTEP(buf, 1);
    }

    // epilogue
#pragma unroll
    for (int mt = 0; mt < MT; mt++) {
        int r0 = bm0 + wm + mt * 16 + gid;
#pragma unroll
        for (int nt = 0; nt < NT; nt++) {
            int c0 = bn0 + wn + nt * 8 + tig * 2;
#pragma unroll
            for (int hf = 0; hf < 2; hf++) {
                int r = r0 + hf * 8;
                float v0 = acc[mt][nt][hf * 2 + 0];
                float v1 = acc[mt][nt][hf * 2 + 1];
                if (mode == 4) {
                    int bb2 = blockIdx.z >> 3, h = blockIdx.z & 7;
                    size_t off = ((size_t)(bb2 * Nc + r)) * HDc + h * DHc + c0;
                    stC(C + off, v0, v1);
                } else {
                    size_t off = (size_t)r * ldc + c0;
                    if (mode == 1) { v0 += bias[c0]; v1 += bias[c0 + 1]; }
                    else if (mode == 2) {
                        float2 rr = *(const float2*)(resid + off);
                        v0 += bias[c0] + rr.x; v1 += bias[c0 + 1] + rr.y;
                    } else if (mode == 3) {
                        v0 += bias[c0]; v1 += bias[c0 + 1];
                        v0 = 0.5f * v0 * (1.f + erff(v0 * 0.70710678118654752f));
                        v1 = 0.5f * v1 * (1.f + erff(v1 * 0.70710678118654752f));
                    }
                    stC(Cb + off, v0, v1);
                }
            }
        }
    }
}

// ---------------- LayerNorm: f32 in -> half out -------------------------------------
__global__ __launch_bounds__(128) void ln_kernel(
    const float* __restrict__ in, __half* __restrict__ out,
    const float* __restrict__ g, const float* __restrict__ bta)
{
    int row = blockIdx.x;
    const float* xr = in + (size_t)row * Dc;
    __half* orow = out + (size_t)row * Dc;
    int tid = threadIdx.x;
    float4 v = *(const float4*)(xr + tid * 4);
    float s = v.x + v.y + v.z + v.w;
    float ss = v.x*v.x + v.y*v.y + v.z*v.z + v.w*v.w;
#pragma unroll
    for (int o = 16; o > 0; o >>= 1) {
        s  += __shfl_xor_sync(0xffffffffu, s, o);
        ss += __shfl_xor_sync(0xffffffffu, ss, o);
    }
    __shared__ float sh[8];
    int w = tid >> 5, lane = tid & 31;
    if (lane == 0) { sh[w] = s; sh[4+w] = ss; }
    __syncthreads();
    if (tid == 0) {
        sh[0] = sh[0]+sh[1]+sh[2]+sh[3];
        sh[1] = sh[4]+sh[5]+sh[6]+sh[7];
    }
    __syncthreads();
    float mean = sh[0] * (1.f/Dc);
    float var  = sh[1] * (1.f/Dc) - mean*mean;
    float inv  = rsqrtf(var + 1e-5f);
    int c = tid * 4;
    float4 gg = *(const float4*)(g + c);
    float4 bb = *(const float4*)(bta + c);
    float y0 = (v.x-mean)*inv*gg.x + bb.x;
    float y1 = (v.y-mean)*inv*gg.y + bb.y;
    float y2 = (v.z-mean)*inv*gg.z + bb.z;
    float y3 = (v.w-mean)*inv*gg.w + bb.w;
    ((__half2*)orow)[tid*2]   = __floats2half2_rn(y0, y1);
    ((__half2*)orow)[tid*2+1] = __floats2half2_rn(y2, y3);
}

// ---------------- weight f32 -> half ------------------------------------------------
__global__ void wh_kernel(const float* __restrict__ in, __half* __restrict__ out)
{
    int i = blockIdx.x * blockDim.x + threadIdx.x;
    float4 t = ((const float4*)in)[i];
    ((__half2*)out)[i*2]   = __floats2half2_rn(t.x, t.y);
    ((__half2*)out)[i*2+1] = __floats2half2_rn(t.z, t.w);
}

// ---------------- split qkv: q(+bias_pf), k -> kw rows [0,1024), v ------------------
__global__ void split_qkv_kernel(
    const float* __restrict__ qkv, const float* __restrict__ bias_pf,
    __half* __restrict__ q, __half* __restrict__ kw, __half* __restrict__ v)
{
    int idx = blockIdx.x * blockDim.x + threadIdx.x;  // B*H*N*(DH/4)
    int d4 = idx & 15;
    int n = (idx >> 4) & (Nc - 1);
    int h = (idx >> 14) & 7;
    int b = idx >> 17;
    int bh = b * Hc + h;
    size_t src = ((size_t)(b*Nc + n)) * (3*HDc) + h*DHc + d4*4;
    float4 qv = *(const float4*)(qkv + src);
    float4 bp = *(const float4*)(bias_pf + h*DHc + d4*4);
    size_t qd = ((size_t)bh * Nc + n) * DHc + d4*4;
    ((__half2*)(q + qd))[0] = __floats2half2_rn(qv.x + bp.x, qv.y + bp.y);
    ((__half2*)(q + qd))[1] = __floats2half2_rn(qv.z + bp.z, qv.w + bp.w);
    float4 kv = *(const float4*)(qkv + src + HDc);
    size_t kd = ((size_t)bh * 2 * Nc + n) * DHc + d4*4;
    ((__half2*)(kw + kd))[0] = __floats2half2_rn(kv.x, kv.y);
    ((__half2*)(kw + kd))[1] = __floats2half2_rn(kv.z, kv.w);
    float4 vv = *(const float4*)(qkv + src + 2*HDc);
    ((__half2*)(v + qd))[0] = __floats2half2_rn(vv.x, vv.y);
    ((__half2*)(v + qd))[1] = __floats2half2_rn(vv.z, vv.w);
}

// ---------------- per-layer: wsall cols -> kw rows [1024,2048), /3 ------------------
__global__ void wsr_layer_kernel(const float* __restrict__ wsall,
                                 __half* __restrict__ kw, int l)
{
    int idx = blockIdx.x * blockDim.x + threadIdx.x;  // B*H*N*(DH/4)
    int d4 = idx & 15;
    int n = (idx >> 4) & (Nc - 1);
    int h = (idx >> 14) & 7;
    int b = idx >> 17;
    int bh = b * Hc + h;
    float4 t = *(const float4*)(wsall + ((size_t)(b*Nc + n)) * 2048 + l*512 + h*64 + d4*4);
    size_t kd = ((size_t)bh * 2 * Nc + Nc + n) * DHc + d4*4;
    ((__half2*)(kw + kd))[0] = __floats2half2_rn(t.x*(1.f/3.f), t.y*(1.f/3.f));
    ((__half2*)(kw + kd))[1] = __floats2half2_rn(t.z*(1.f/3.f), t.w*(1.f/3.f));
}

// ---------------- build [r_t|r_c|r_p] half ------------------------------------------
__global__ void rcat_kernel(const float* __restrict__ rt, const float* __restrict__ rc,
                            const float* __restrict__ rp, __half* __restrict__ out)
{
    int idx = blockIdx.x * blockDim.x + threadIdx.x;
    int row = idx / 384, c4 = idx % 384;
    const float* srcs[3] = {rt, rc, rp};
    const float* s = srcs[c4 >> 7];
    int c = (c4 & 127) * 4;
    float4 t = *(const float4*)(s + (size_t)row*512 + c);
    ((__half2*)out)[idx*2]   = __floats2half2_rn(t.x, t.y);
    ((__half2*)out)[idx*2+1] = __floats2half2_rn(t.z, t.w);
}

// ---------------- build stacked W half (1536 x 2048) --------------------------------
__global__ void wall_kernel(const float* __restrict__ wkt, const float* __restrict__ wkc,
                            const float* __restrict__ wkp, __half* __restrict__ out)
{
    int idx = blockIdx.x * blockDim.x + threadIdx.x;
    int k = idx >> 9;
    int col4 = idx & 511;
    int l = col4 >> 7, c = (col4 & 127) * 4;
    const float* srcs[3] = {wkt, wkc, wkp};
    const float* s = srcs[k >> 9];
    int kk = k & 511;
    float4 t = *(const float4*)(s + ((size_t)l*512 + kk) * 512 + c);
    ((__half2*)out)[idx*2]   = __floats2half2_rn(t.x, t.y);
    ((__half2*)out)[idx*2+1] = __floats2half2_rn(t.z, t.w);
}

// ---------------- fused combine + rel_shift + softmax over heads --------------------
__global__ void softmax_fused_kernel(const float* __restrict__ sc,
                                     __half* __restrict__ attn,
                                     float* __restrict__ attn_raw)
{
    int t = blockIdx.x * blockDim.x + threadIdx.x;   // B*N*(N/4)
    int j4 = (t & 255) * 4;
    int i = (t >> 8) & (Nc - 1);
    int b = t >> 18;
    size_t scb = ((size_t)(b * Hc)) << 21;           // bh stride = 1024*2048 = 2^21
    float d[Hc][4];
#pragma unroll
    for (int h = 0; h < Hc; h++) {
        float4 acv = *(const float4*)(sc + scb + ((size_t)h << 21) + (size_t)i * 2048 + j4);
        d[h][0] = acv.x; d[h][1] = acv.y; d[h][2] = acv.z; d[h][3] = acv.w;
    }
#pragma unroll
    for (int e = 0; e < 4; e++) {
        int j = j4 + e;
        int f = i * Nc + j + Nc;
        int i2 = f / (Nc + 1);
        int jj = f - i2 * (Nc + 1);
        if (jj != 0) {
            size_t bd = scb + (size_t)i2 * 2048 + Nc + (jj - 1);
#pragma unroll
            for (int h = 0; h < Hc; h++)
                d[h][e] = (d[h][e] + sc[bd + ((size_t)h << 21)]) * SCALEc;
        } else {
#pragma unroll
            for (int h = 0; h < Hc; h++) d[h][e] *= SCALEc;
        }
    }
#pragma unroll
    for (int e = 0; e < 4; e++) {
        float m = d[0][e];
#pragma unroll
        for (int h = 1; h < Hc; h++) m = fmaxf(m, d[h][e]);
        float s = 0.f;
#pragma unroll
        for (int h = 0; h < Hc; h++) { d[h][e] = expf(d[h][e] - m); s += d[h][e]; }
        float inv = 1.f / s;
#pragma unroll
        for (int h = 0; h < Hc; h++) d[h][e] *= inv;
    }
    size_t abase = (((size_t)(b * Hc)) << 20) + (size_t)i * Nc + j4;
#pragma unroll
    for (int h = 0; h < Hc; h++) {
        size_t o = abase + ((size_t)h << 20);
        if (attn_raw) {
            float4 r; r.x = d[h][0]; r.y = d[h][1]; r.z = d[h][2]; r.w = d[h][3];
            *(float4*)(attn_raw + o) = r;
        }
        ((__half2*)(attn + o))[0] = __floats2half2_rn(d[h][0], d[h][1]);
        ((__half2*)(attn + o))[1] = __floats2half2_rn(d[h][2], d[h][3]);
    }
}

// ===================================================================================
extern "C" void kernel_launch(void* const* d_in, const int* in_sizes, int n_in,
                              void* d_out, int out_size)
{
    const float* x_in    = (const float*)d_in[0];
    const float* r_t     = (const float*)d_in[1];
    const float* r_c     = (const float*)d_in[2];
    const float* r_p     = (const float*)d_in[3];
    const float* bias_pf = (const float*)d_in[4];
    const float* ln1_g   = (const float*)d_in[5];
    const float* ln1_b   = (const float*)d_in[6];
    const float* w_qkv   = (const float*)d_in[7];
    const float* w_out   = (const float*)d_in[8];
    const float* b_out   = (const float*)d_in[9];
    const float* w_kt    = (const float*)d_in[10];
    const float* w_kc    = (const float*)d_in[11];
    const float* w_kp    = (const float*)d_in[12];
    const float* ln2_g   = (const float*)d_in[13];
    const float* ln2_b   = (const float*)d_in[14];
    const float* w_ff1   = (const float*)d_in[15];
    const float* b_ff1   = (const float*)d_in[16];
    const float* w_ff2   = (const float*)d_in[17];
    const float* b_ff2   = (const float*)d_in[18];
    float* out = (float*)d_out;

    __half *xn, *q, *kw, *v, *rcat, *wall, *attnb, *av, *h1, *wqkvh, *wouth, *wff1h, *wff2h;
    float *qkv, *wsall, *sc, *x, *xmid;
    cudaGetSymbolAddress((void**)&xn, g_xn);
    cudaGetSymbolAddress((void**)&qkv, g_qkv);
    cudaGetSymbolAddress((void**)&q, g_q);
    cudaGetSymbolAddress((void**)&kw, g_kw);
    cudaGetSymbolAddress((void**)&v, g_v);
    cudaGetSymbolAddress((void**)&rcat, g_rcat);
    cudaGetSymbolAddress((void**)&wall, g_wall);
    cudaGetSymbolAddress((void**)&wsall, g_wsall);
    cudaGetSymbolAddress((void**)&sc, g_sc);
    cudaGetSymbolAddress((void**)&attnb, g_attn);
    cudaGetSymbolAddress((void**)&av, g_av);
    cudaGetSymbolAddress((void**)&h1, g_h1);
    cudaGetSymbolAddress((void**)&x, g_x);
    cudaGetSymbolAddress((void**)&xmid, g_xmid);
    cudaGetSymbolAddress((void**)&wqkvh, g_wqkvh);
    cudaGetSymbolAddress((void**)&wouth, g_wouth);
    cudaGetSymbolAddress((void**)&wff1h, g_wff1h);
    cudaGetSymbolAddress((void**)&wff2h, g_wff2h);

    float* x_out    = out;
    float* attn_out = out + (size_t)Mc * Dc;

    // weight conversions
    wh_kernel<<<(4*Dc*3*HDc/4)/256, 256>>>(w_qkv, wqkvh);
    wh_kernel<<<(4*HDc*Dc/4)/256, 256>>>(w_out, wouth);
    wh_kernel<<<(4*Dc*FFc/4)/256, 256>>>(w_ff1, wff1h);
    wh_kernel<<<(4*FFc*Dc/4)/256, 256>>>(w_ff2, wff2h);

    // upfront all-layer relative projection
    rcat_kernel<<<(Mc*3*Dc/4)/256, 256>>>(r_t, r_c, r_p, rcat);
    wall_kernel<<<(3*Dc*2048/4)/256, 256>>>(w_kt, w_kc, w_kp, wall);
    h_gemm<128,128,64,32,false,float><<<dim3(16,16), 256>>>(
        rcat, wall, wsall, 3*Dc, 3*Dc, 2048, 2048, 0,0,0, nullptr, nullptr, 0);

    const float* cur = x_in;
    for (int l = 0; l < 4; l++) {
        ln_kernel<<<Mc, 128>>>(cur, xn, ln1_g + l*Dc, ln1_b + l*Dc);
        h_gemm<128,128,64,32,false,float><<<dim3(12,16), 256>>>(
            xn, wqkvh + (size_t)l*Dc*3*HDc, qkv, Dc, Dc, 3*HDc, 3*HDc,
            0,0,0, nullptr, nullptr, 0);
        split_qkv_kernel<<<(BHc*Nc*DHc/4)/256, 256>>>(qkv, bias_pf, q, kw, v);
        wsr_layer_kernel<<<(BHc*Nc*DHc/4)/256, 256>>>(wsall, kw, l);
        // combined scores: [AC | BDraw] in one GEMM, N=2048 per bh
        h_gemm<128,128,64,32,true,float><<<dim3(16,8,BHc), 256>>>(
            q, kw, sc, DHc, DHc, DHc, 2*Nc,
            (long long)Nc*DHc, (long long)2*Nc*DHc, (long long)Nc*2*Nc,
            nullptr, nullptr, 0);
        softmax_fused_kernel<<<(int)(((size_t)Bc*Nc*Nc/4)/256), 256>>>(
            sc, attnb, (l == 3) ? attn_out : nullptr);
        h_gemm<64,64,32,16,false,__half><<<dim3(1,16,BHc), 256>>>(
            attnb, v, av, Nc, Nc, DHc, HDc,
            (long long)Nc*Nc, (long long)Nc*DHc, 0,
            nullptr, nullptr, 4);
        h_gemm<64,128,32,32,false,float><<<dim3(4,32), 256>>>(
            av, wouth + (size_t)l*HDc*Dc, xmid, HDc, HDc, Dc, Dc,
            0,0,0, b_out + l*Dc, cur, 2);
        ln_kernel<<<Mc, 128>>>(xmid, xn, ln2_g + l*Dc, ln2_b + l*Dc);
        h_gemm<128,128,64,32,false,__half><<<dim3(16,16), 256>>>(
            xn, wff1h + (size_t)l*Dc*FFc, h1, Dc, Dc, FFc, FFc,
            0,0,0, b_ff1 + l*FFc, nullptr, 3);
        float* xdst = (l == 3) ? x_out : x;
        h_gemm<64,128,32,32,false,float><<<dim3(4,32), 256>>>(
            h1, wff2h + (size_t)l*FFc*Dc, xdst, FFc, FFc, Dc, Dc,
            0,0,0, b_ff2 + l*Dc, xmid, 2);
        cur = x;
    }
}

// round 11
// speedup vs baseline: 2.9822x; 1.1307x over previous
#include <cuda_runtime.h>
#include <cuda_fp16.h>
#include <math.h>
#include <stdint.h>

#define Bc 2
#define Nc 1024
#define Dc 512
#define Hc 8
#define DHc 64
#define HDc 512
#define FFc 2048
#define Mc (Bc*Nc)
#define BHc (Bc*Hc)
#define SCALEc 0.125f

// ---------------- device scratch ----------------------------------------------------
static __device__ __align__(256) __half g_xn[Mc*Dc];
static __device__ __align__(256) float  g_qkv[Mc*3*HDc];
static __device__ __align__(256) __half g_q[BHc*Nc*DHc];
static __device__ __align__(256) __half g_kw[BHc*2*Nc*DHc];   // rows 0..1023 = K, 1024.. = Wsr/3
static __device__ __align__(256) __half g_v[BHc*Nc*DHc];
static __device__ __align__(256) __half g_rcat[Mc*3*Dc];
static __device__ __align__(256) __half g_wall[3*Dc*4*HDc];
static __device__ __align__(256) float  g_wsall[Mc*4*HDc];
static __device__ __align__(256) __half g_sc[(size_t)BHc*Nc*2*Nc];   // fp16 scores [bh][i][2048]
static __device__ __align__(256) __half g_attn[(size_t)BHc*Nc*Nc];
static __device__ __align__(256) __half g_av[Mc*HDc];
static __device__ __align__(256) __half g_h1[Mc*FFc];
static __device__ __align__(256) float  g_x[Mc*Dc];
static __device__ __align__(256) float  g_xmid[Mc*Dc];
static __device__ __align__(256) __half g_wqkvh[4*Dc*3*HDc];
static __device__ __align__(256) __half g_wouth[4*HDc*Dc];
static __device__ __align__(256) __half g_wff1h[4*Dc*FFc];
static __device__ __align__(256) __half g_wff2h[4*FFc*Dc];

// ---------------- asm helpers -------------------------------------------------------
__device__ __forceinline__ void mma16(float* c, const unsigned* a, const unsigned* b) {
    asm volatile("mma.sync.aligned.m16n8k16.row.col.f32.f16.f16.f32 "
        "{%0,%1,%2,%3}, {%4,%5,%6,%7}, {%8,%9}, {%0,%1,%2,%3};"
        : "+f"(c[0]), "+f"(c[1]), "+f"(c[2]), "+f"(c[3])
        : "r"(a[0]), "r"(a[1]), "r"(a[2]), "r"(a[3]), "r"(b[0]), "r"(b[1]));
}
__device__ __forceinline__ void ldm_x4(unsigned* r, unsigned addr) {
    asm volatile("ldmatrix.sync.aligned.m8n8.x4.shared.b16 {%0,%1,%2,%3}, [%4];"
        : "=r"(r[0]), "=r"(r[1]), "=r"(r[2]), "=r"(r[3]) : "r"(addr));
}
__device__ __forceinline__ void ldm_x2(unsigned* r, unsigned addr) {
    asm volatile("ldmatrix.sync.aligned.m8n8.x2.shared.b16 {%0,%1}, [%2];"
        : "=r"(r[0]), "=r"(r[1]) : "r"(addr));
}
__device__ __forceinline__ void ldm_x2t(unsigned* r, unsigned addr) {
    asm volatile("ldmatrix.sync.aligned.m8n8.x2.trans.shared.b16 {%0,%1}, [%2];"
        : "=r"(r[0]), "=r"(r[1]) : "r"(addr));
}
__device__ __forceinline__ void cp16s(unsigned dst, const void* src) {
    asm volatile("cp.async.cg.shared.global [%0], [%1], 16;\n" :: "r"(dst), "l"(src));
}
#define CP_COMMIT() asm volatile("cp.async.commit_group;\n" ::: "memory")
template<int N> __device__ __forceinline__ void cp_wait() {
    asm volatile("cp.async.wait_group %0;\n" :: "n"(N) : "memory");
}

__device__ __forceinline__ void stC(float* p, float v0, float v1) {
    *(float2*)p = make_float2(v0, v1);
}
__device__ __forceinline__ void stC(__half* p, float v0, float v1) {
    *(__half2*)p = __floats2half2_rn(v0, v1);
}

// ---------------- fp16 tensor-core GEMM (m16n8k16 + ldmatrix + cp.async xNS) --------
// C(MxN) = A(MxK) @ op(B).  TB=false: B KxN row-major; TB=true: B NxK row-major.
// mode: 0 plain, 1 +bias, 2 +bias+resid(f32), 3 +bias,gelu, 4 attn_v scatter epilogue
template<int BM, int BN, int WM, int WN, bool TB, typename CT, int NS>
__global__ __launch_bounds__(256, 2) void h_gemm(
    const __half* __restrict__ A, const __half* __restrict__ B, CT* __restrict__ C,
    int K, int lda, int ldb, int ldc,
    long long sA, long long sB, long long sC,
    const float* __restrict__ bias, const float* __restrict__ resid, int mode)
{
    constexpr int NWN = BN / WN;
    constexpr int MT = WM / 16;
    constexpr int NT = WN / 8;
    constexpr int IAc = (BM * 4) / 256;
    constexpr int IBc = (BN * 4) / 256;
    __shared__ __half As[NS][BM * 32];
    __shared__ __half Bs[NS][BN * 32];

    const __half* Ab = A + (size_t)sA * blockIdx.z;
    const __half* Bb = B + (size_t)sB * blockIdx.z;
    CT* Cb = C + (size_t)sC * blockIdx.z;

    int tid = threadIdx.x;
    int lane = tid & 31, wid = tid >> 5;
    int wm = (wid / NWN) * WM, wn = (wid % NWN) * WN;
    int gid = lane >> 2, tig = lane & 3;
    int bm0 = blockIdx.y * BM, bn0 = blockIdx.x * BN;

    unsigned sAs = (unsigned)__cvta_generic_to_shared(&As[0][0]);
    unsigned sBs = (unsigned)__cvta_generic_to_shared(&Bs[0][0]);

    float acc[MT][NT][4];
#pragma unroll
    for (int i = 0; i < MT; i++)
#pragma unroll
        for (int j = 0; j < NT; j++)
#pragma unroll
            for (int t = 0; t < 4; t++) acc[i][j][t] = 0.f;

    auto MOD = [](int x) { return ((NS & (NS - 1)) == 0) ? (x & (NS - 1)) : (x % NS); };

    auto COPY = [&](int st, int k0) {
#pragma unroll
        for (int it = 0; it < IAc; it++) {
            int ch = tid + it * 256;
            int m = ch >> 2, c = ch & 3;
            int cc = c ^ ((m >> 1) & 3);
            cp16s(sAs + (st * BM * 32 + m * 32 + cc * 8) * 2,
                  Ab + (size_t)(bm0 + m) * lda + k0 + c * 8);
        }
        if (TB) {
#pragma unroll
            for (int it = 0; it < IBc; it++) {
                int ch = tid + it * 256;
                int n = ch >> 2, c = ch & 3;
                int cc = c ^ ((n >> 1) & 3);
                cp16s(sBs + (st * BN * 32 + n * 32 + cc * 8) * 2,
                      Bb + (size_t)(bn0 + n) * ldb + k0 + c * 8);
            }
        } else {
#pragma unroll
            for (int it = 0; it < IBc; it++) {
                int ch = tid + it * 256;
                int k = ch / (BN / 8), nc = ch % (BN / 8);
                int cc = nc ^ (k & 7);
                cp16s(sBs + (st * BN * 32 + k * BN + cc * 8) * 2,
                      Bb + (size_t)(k0 + k) * ldb + bn0 + nc * 8);
            }
        }
    };
    auto MMASTEP = [&](int st, int s) {
        unsigned af[MT][4], bf[NT][2];
        unsigned abase = sAs + st * (BM * 32 * 2);
        unsigned bbase = sBs + st * (BN * 32 * 2);
        int la = lane & 7, t4 = lane >> 3;
#pragma unroll
        for (int mt = 0; mt < MT; mt++) {
            int m = wm + mt * 16 + (t4 & 1) * 8 + la;
            int c = 2 * s + (t4 >> 1);
            ldm_x4(af[mt], abase + (m * 32 + ((c ^ ((m >> 1) & 3)) << 3)) * 2);
        }
        if (TB) {
            int l2 = lane & 15;
#pragma unroll
            for (int nt = 0; nt < NT; nt++) {
                int n = wn + nt * 8 + (l2 & 7);
                int c = 2 * s + (l2 >> 3);
                ldm_x2(bf[nt], bbase + (n * 32 + ((c ^ ((n >> 1) & 3)) << 3)) * 2);
            }
        } else {
            int kk = 16 * s + (lane & 15);
#pragma unroll
            for (int nt = 0; nt < NT; nt++) {
                int nc = (wn + nt * 8) >> 3;
                ldm_x2t(bf[nt], bbase + (kk * BN + ((nc ^ (kk & 7)) << 3)) * 2);
            }
        }
#pragma unroll
        for (int mt = 0; mt < MT; mt++)
#pragma unroll
            for (int nt = 0; nt < NT; nt++)
                mma16(acc[mt][nt], af[mt], bf[nt]);
    };

    int nk = K >> 5;
#pragma unroll
    for (int s = 0; s < NS - 1; s++) {
        if (nk > s) COPY(s, s << 5);
        CP_COMMIT();
    }
    for (int kt = 0; kt < nk; kt++) {
        cp_wait<NS - 2>();
        __syncthreads();
        int nxt = kt + NS - 1;
        if (nxt < nk) COPY(MOD(nxt), nxt << 5);
        CP_COMMIT();
        int buf = MOD(kt);
        MMASTEP(buf, 0);
        MMASTEP(buf, 1);
    }

    // epilogue
#pragma unroll
    for (int mt = 0; mt < MT; mt++) {
        int r0 = bm0 + wm + mt * 16 + gid;
#pragma unroll
        for (int nt = 0; nt < NT; nt++) {
            int c0 = bn0 + wn + nt * 8 + tig * 2;
#pragma unroll
            for (int hf = 0; hf < 2; hf++) {
                int r = r0 + hf * 8;
                float v0 = acc[mt][nt][hf * 2 + 0];
                float v1 = acc[mt][nt][hf * 2 + 1];
                if (mode == 4) {
                    int bb2 = blockIdx.z >> 3, h = blockIdx.z & 7;
                    size_t off = ((size_t)(bb2 * Nc + r)) * HDc + h * DHc + c0;
                    stC(C + off, v0, v1);
                } else {
                    size_t off = (size_t)r * ldc + c0;
                    if (mode == 1) { v0 += bias[c0]; v1 += bias[c0 + 1]; }
                    else if (mode == 2) {
                        float2 rr = *(const float2*)(resid + off);
                        v0 += bias[c0] + rr.x; v1 += bias[c0 + 1] + rr.y;
                    } else if (mode == 3) {
                        v0 += bias[c0]; v1 += bias[c0 + 1];
                        v0 = 0.5f * v0 * (1.f + erff(v0 * 0.70710678118654752f));
                        v1 = 0.5f * v1 * (1.f + erff(v1 * 0.70710678118654752f));
                    }
                    stC(Cb + off, v0, v1);
                }
            }
        }
    }
}

// ---------------- LayerNorm: f32 in -> half out -------------------------------------
__global__ __launch_bounds__(128) void ln_kernel(
    const float* __restrict__ in, __half* __restrict__ out,
    const float* __restrict__ g, const float* __restrict__ bta)
{
    int row = blockIdx.x;
    const float* xr = in + (size_t)row * Dc;
    __half* orow = out + (size_t)row * Dc;
    int tid = threadIdx.x;
    float4 v = *(const float4*)(xr + tid * 4);
    float s = v.x + v.y + v.z + v.w;
    float ss = v.x*v.x + v.y*v.y + v.z*v.z + v.w*v.w;
#pragma unroll
    for (int o = 16; o > 0; o >>= 1) {
        s  += __shfl_xor_sync(0xffffffffu, s, o);
        ss += __shfl_xor_sync(0xffffffffu, ss, o);
    }
    __shared__ float sh[8];
    int w = tid >> 5, lane = tid & 31;
    if (lane == 0) { sh[w] = s; sh[4+w] = ss; }
    __syncthreads();
    if (tid == 0) {
        sh[0] = sh[0]+sh[1]+sh[2]+sh[3];
        sh[1] = sh[4]+sh[5]+sh[6]+sh[7];
    }
    __syncthreads();
    float mean = sh[0] * (1.f/Dc);
    float var  = sh[1] * (1.f/Dc) - mean*mean;
    float inv  = rsqrtf(var + 1e-5f);
    int c = tid * 4;
    float4 gg = *(const float4*)(g + c);
    float4 bb = *(const float4*)(bta + c);
    float y0 = (v.x-mean)*inv*gg.x + bb.x;
    float y1 = (v.y-mean)*inv*gg.y + bb.y;
    float y2 = (v.z-mean)*inv*gg.z + bb.z;
    float y3 = (v.w-mean)*inv*gg.w + bb.w;
    ((__half2*)orow)[tid*2]   = __floats2half2_rn(y0, y1);
    ((__half2*)orow)[tid*2+1] = __floats2half2_rn(y2, y3);
}

// ---------------- weight f32 -> half ------------------------------------------------
__global__ void wh_kernel(const float* __restrict__ in, __half* __restrict__ out)
{
    int i = blockIdx.x * blockDim.x + threadIdx.x;
    float4 t = ((const float4*)in)[i];
    ((__half2*)out)[i*2]   = __floats2half2_rn(t.x, t.y);
    ((__half2*)out)[i*2+1] = __floats2half2_rn(t.z, t.w);
}

// ---------------- split qkv: q(+bias_pf), k -> kw rows [0,1024), v ------------------
__global__ void split_qkv_kernel(
    const float* __restrict__ qkv, const float* __restrict__ bias_pf,
    __half* __restrict__ q, __half* __restrict__ kw, __half* __restrict__ v)
{
    int idx = blockIdx.x * blockDim.x + threadIdx.x;  // B*H*N*(DH/4)
    int d4 = idx & 15;
    int n = (idx >> 4) & (Nc - 1);
    int h = (idx >> 14) & 7;
    int b = idx >> 17;
    int bh = b * Hc + h;
    size_t src = ((size_t)(b*Nc + n)) * (3*HDc) + h*DHc + d4*4;
    float4 qv = *(const float4*)(qkv + src);
    float4 bp = *(const float4*)(bias_pf + h*DHc + d4*4);
    size_t qd = ((size_t)bh * Nc + n) * DHc + d4*4;
    ((__half2*)(q + qd))[0] = __floats2half2_rn(qv.x + bp.x, qv.y + bp.y);
    ((__half2*)(q + qd))[1] = __floats2half2_rn(qv.z + bp.z, qv.w + bp.w);
    float4 kv = *(const float4*)(qkv + src + HDc);
    size_t kd = ((size_t)bh * 2 * Nc + n) * DHc + d4*4;
    ((__half2*)(kw + kd))[0] = __floats2half2_rn(kv.x, kv.y);
    ((__half2*)(kw + kd))[1] = __floats2half2_rn(kv.z, kv.w);
    float4 vv = *(const float4*)(qkv + src + 2*HDc);
    ((__half2*)(v + qd))[0] = __floats2half2_rn(vv.x, vv.y);
    ((__half2*)(v + qd))[1] = __floats2half2_rn(vv.z, vv.w);
}

// ---------------- per-layer: wsall cols -> kw rows [1024,2048), /3 ------------------
__global__ void wsr_layer_kernel(const float* __restrict__ wsall,
                                 __half* __restrict__ kw, int l)
{
    int idx = blockIdx.x * blockDim.x + threadIdx.x;
    int d4 = idx & 15;
    int n = (idx >> 4) & (Nc - 1);
    int h = (idx >> 14) & 7;
    int b = idx >> 17;
    int bh = b * Hc + h;
    float4 t = *(const float4*)(wsall + ((size_t)(b*Nc + n)) * 2048 + l*512 + h*64 + d4*4);
    size_t kd = ((size_t)bh * 2 * Nc + Nc + n) * DHc + d4*4;
    ((__half2*)(kw + kd))[0] = __floats2half2_rn(t.x*(1.f/3.f), t.y*(1.f/3.f));
    ((__half2*)(kw + kd))[1] = __floats2half2_rn(t.z*(1.f/3.f), t.w*(1.f/3.f));
}

// ---------------- build [r_t|r_c|r_p] half ------------------------------------------
__global__ void rcat_kernel(const float* __restrict__ rt, const float* __restrict__ rc,
                            const float* __restrict__ rp, __half* __restrict__ out)
{
    int idx = blockIdx.x * blockDim.x + threadIdx.x;
    int row = idx / 384, c4 = idx % 384;
    const float* srcs[3] = {rt, rc, rp};
    const float* s = srcs[c4 >> 7];
    int c = (c4 & 127) * 4;
    float4 t = *(const float4*)(s + (size_t)row*512 + c);
    ((__half2*)out)[idx*2]   = __floats2half2_rn(t.x, t.y);
    ((__half2*)out)[idx*2+1] = __floats2half2_rn(t.z, t.w);
}

// ---------------- build stacked W half (1536 x 2048) --------------------------------
__global__ void wall_kernel(const float* __restrict__ wkt, const float* __restrict__ wkc,
                            const float* __restrict__ wkp, __half* __restrict__ out)
{
    int idx = blockIdx.x * blockDim.x + threadIdx.x;
    int k = idx >> 9;
    int col4 = idx & 511;
    int l = col4 >> 7, c = (col4 & 127) * 4;
    const float* srcs[3] = {wkt, wkc, wkp};
    const float* s = srcs[k >> 9];
    int kk = k & 511;
    float4 t = *(const float4*)(s + ((size_t)l*512 + kk) * 512 + c);
    ((__half2*)out)[idx*2]   = __floats2half2_rn(t.x, t.y);
    ((__half2*)out)[idx*2+1] = __floats2half2_rn(t.z, t.w);
}

// ---------------- fused combine + rel_shift + softmax over heads (fp16 scores) ------
__global__ void softmax_fused_kernel(const __half* __restrict__ sc,
                                     __half* __restrict__ attn,
                                     float* __restrict__ attn_raw)
{
    int t = blockIdx.x * blockDim.x + threadIdx.x;   // B*N*(N/4)
    int j4 = (t & 255) * 4;
    int i = (t >> 8) & (Nc - 1);
    int b = t >> 18;
    size_t scb = ((size_t)(b * Hc)) << 21;           // bh stride = 1024*2048 = 2^21
    float d[Hc][4];
#pragma unroll
    for (int h = 0; h < Hc; h++) {
        const __half2* p = (const __half2*)(sc + scb + ((size_t)h << 21) + (size_t)i * 2048 + j4);
        float2 a0 = __half22float2(p[0]);
        float2 a1 = __half22float2(p[1]);
        d[h][0] = a0.x; d[h][1] = a0.y; d[h][2] = a1.x; d[h][3] = a1.y;
    }
#pragma unroll
    for (int e = 0; e < 4; e++) {
        int j = j4 + e;
        int f = i * Nc + j + Nc;
        int i2 = f / (Nc + 1);
        int jj = f - i2 * (Nc + 1);
        if (jj != 0) {
            size_t bd = scb + (size_t)i2 * 2048 + Nc + (jj - 1);
#pragma unroll
            for (int h = 0; h < Hc; h++)
                d[h][e] = (d[h][e] + __half2float(sc[bd + ((size_t)h << 21)])) * SCALEc;
        } else {
#pragma unroll
            for (int h = 0; h < Hc; h++) d[h][e] *= SCALEc;
        }
    }
#pragma unroll
    for (int e = 0; e < 4; e++) {
        float m = d[0][e];
#pragma unroll
        for (int h = 1; h < Hc; h++) m = fmaxf(m, d[h][e]);
        float s = 0.f;
#pragma unroll
        for (int h = 0; h < Hc; h++) { d[h][e] = expf(d[h][e] - m); s += d[h][e]; }
        float inv = 1.f / s;
#pragma unroll
        for (int h = 0; h < Hc; h++) d[h][e] *= inv;
    }
    size_t abase = (((size_t)(b * Hc)) << 20) + (size_t)i * Nc + j4;
#pragma unroll
    for (int h = 0; h < Hc; h++) {
        size_t o = abase + ((size_t)h << 20);
        if (attn_raw) {
            float4 r; r.x = d[h][0]; r.y = d[h][1]; r.z = d[h][2]; r.w = d[h][3];
            *(float4*)(attn_raw + o) = r;
        }
        ((__half2*)(attn + o))[0] = __floats2half2_rn(d[h][0], d[h][1]);
        ((__half2*)(attn + o))[1] = __floats2half2_rn(d[h][2], d[h][3]);
    }
}

// ===================================================================================
extern "C" void kernel_launch(void* const* d_in, const int* in_sizes, int n_in,
                              void* d_out, int out_size)
{
    const float* x_in    = (const float*)d_in[0];
    const float* r_t     = (const float*)d_in[1];
    const float* r_c     = (const float*)d_in[2];
    const float* r_p     = (const float*)d_in[3];
    const float* bias_pf = (const float*)d_in[4];
    const float* ln1_g   = (const float*)d_in[5];
    const float* ln1_b   = (const float*)d_in[6];
    const float* w_qkv   = (const float*)d_in[7];
    const float* w_out   = (const float*)d_in[8];
    const float* b_out   = (const float*)d_in[9];
    const float* w_kt    = (const float*)d_in[10];
    const float* w_kc    = (const float*)d_in[11];
    const float* w_kp    = (const float*)d_in[12];
    const float* ln2_g   = (const float*)d_in[13];
    const float* ln2_b   = (const float*)d_in[14];
    const float* w_ff1   = (const float*)d_in[15];
    const float* b_ff1   = (const float*)d_in[16];
    const float* w_ff2   = (const float*)d_in[17];
    const float* b_ff2   = (const float*)d_in[18];
    float* out = (float*)d_out;

    __half *xn, *q, *kw, *v, *rcat, *wall, *sc, *attnb, *av, *h1,
           *wqkvh, *wouth, *wff1h, *wff2h;
    float *qkv, *wsall, *x, *xmid;
    cudaGetSymbolAddress((void**)&xn, g_xn);
    cudaGetSymbolAddress((void**)&qkv, g_qkv);
    cudaGetSymbolAddress((void**)&q, g_q);
    cudaGetSymbolAddress((void**)&kw, g_kw);
    cudaGetSymbolAddress((void**)&v, g_v);
    cudaGetSymbolAddress((void**)&rcat, g_rcat);
    cudaGetSymbolAddress((void**)&wall, g_wall);
    cudaGetSymbolAddress((void**)&wsall, g_wsall);
    cudaGetSymbolAddress((void**)&sc, g_sc);
    cudaGetSymbolAddress((void**)&attnb, g_attn);
    cudaGetSymbolAddress((void**)&av, g_av);
    cudaGetSymbolAddress((void**)&h1, g_h1);
    cudaGetSymbolAddress((void**)&x, g_x);
    cudaGetSymbolAddress((void**)&xmid, g_xmid);
    cudaGetSymbolAddress((void**)&wqkvh, g_wqkvh);
    cudaGetSymbolAddress((void**)&wouth, g_wouth);
    cudaGetSymbolAddress((void**)&wff1h, g_wff1h);
    cudaGetSymbolAddress((void**)&wff2h, g_wff2h);

    float* x_out    = out;
    float* attn_out = out + (size_t)Mc * Dc;

    // weight conversions
    wh_kernel<<<(4*Dc*3*HDc/4)/256, 256>>>(w_qkv, wqkvh);
    wh_kernel<<<(4*HDc*Dc/4)/256, 256>>>(w_out, wouth);
    wh_kernel<<<(4*Dc*FFc/4)/256, 256>>>(w_ff1, wff1h);
    wh_kernel<<<(4*FFc*Dc/4)/256, 256>>>(w_ff2, wff2h);

    // upfront all-layer relative projection
    rcat_kernel<<<(Mc*3*Dc/4)/256, 256>>>(r_t, r_c, r_p, rcat);
    wall_kernel<<<(3*Dc*2048/4)/256, 256>>>(w_kt, w_kc, w_kp, wall);
    h_gemm<128,128,64,32,false,float,3><<<dim3(16,16), 256>>>(
        rcat, wall, wsall, 3*Dc, 3*Dc, 2048, 2048, 0,0,0, nullptr, nullptr, 0);

    const float* cur = x_in;
    for (int l = 0; l < 4; l++) {
        ln_kernel<<<Mc, 128>>>(cur, xn, ln1_g + l*Dc, ln1_b + l*Dc);
        h_gemm<128,128,64,32,false,float,3><<<dim3(12,16), 256>>>(
            xn, wqkvh + (size_t)l*Dc*3*HDc, qkv, Dc, Dc, 3*HDc, 3*HDc,
            0,0,0, nullptr, nullptr, 0);
        split_qkv_kernel<<<(BHc*Nc*DHc/4)/256, 256>>>(qkv, bias_pf, q, kw, v);
        wsr_layer_kernel<<<(BHc*Nc*DHc/4)/256, 256>>>(wsall, kw, l);
        // combined scores: [AC | BDraw] in one GEMM, N=2048 per bh, fp16 out
        h_gemm<128,128,64,32,true,__half,3><<<dim3(16,8,BHc), 256>>>(
            q, kw, sc, DHc, DHc, DHc, 2*Nc,
            (long long)Nc*DHc, (long long)2*Nc*DHc, (long long)Nc*2*Nc,
            nullptr, nullptr, 0);
        softmax_fused_kernel<<<(int)(((size_t)Bc*Nc*Nc/4)/256), 256>>>(
            sc, attnb, (l == 3) ? attn_out : nullptr);
        h_gemm<64,64,32,16,false,__half,4><<<dim3(1,16,BHc), 256>>>(
            attnb, v, av, Nc, Nc, DHc, HDc,
            (long long)Nc*Nc, (long long)Nc*DHc, 0,
            nullptr, nullptr, 4);
        h_gemm<64,64,32,16,false,float,4><<<dim3(8,32), 256>>>(
            av, wouth + (size_t)l*HDc*Dc, xmid, HDc, HDc, Dc, Dc,
            0,0,0, b_out + l*Dc, cur, 2);
        ln_kernel<<<Mc, 128>>>(xmid, xn, ln2_g + l*Dc, ln2_b + l*Dc);
        h_gemm<128,128,64,32,false,__half,3><<<dim3(16,16), 256>>>(
            xn, wff1h + (size_t)l*Dc*FFc, h1, Dc, Dc, FFc, FFc,
            0,0,0, b_ff1 + l*FFc, nullptr, 3);
        float* xdst = (l == 3) ? x_out : x;
        h_gemm<64,64,32,16,false,float,4><<<dim3(8,32), 256>>>(
            h1, wff2h + (size_t)l*FFc*Dc, xdst, FFc, FFc, Dc, Dc,
            0,0,0, b_ff2 + l*Dc, xmid, 2);
        cur = x;
    }
}